// round 14
// baseline (speedup 1.0000x reference)
#include <cuda_runtime.h>
#include <cuda_fp16.h>
#include <cstdint>

#define L_   197
#define LP_  200
#define NB_  128
#define E_   768
#define H_   12
#define HD_  64
#define B_   1536
#define NS_  60
#define LT_  257
#define OUT_ELEMS 25264128
#define AW_ELEMS  6480512

#define STRH 40        // proj/out smem row stride in halves (80 B)
#define STR2 72        // qk/av smem row stride in halves (144 B)

#define IN_ELEMS 19365888        // 25216*768
#define W_ELEMS  589824          // 768*768
#define DESCALE 0.00390625f      // 2^-8

// ---------------- scratch ----------------
__device__ float  g_attn[78950400];      // (B, LT, LP_) RAW scores (fp32)
__device__ __half g_p16[78950400];       // (B, LT, LP_) post-softmax probs (fp16)
__device__ __half g_ah[3*IN_ELEMS];      // inputs rounded to fp16 (proj A)
__device__ __half g_wh[4*W_ELEMS];       // weights*256 hi
__device__ __half g_wl[4*W_ELEMS];       // weights*256 lo
__device__ __half g_qh[IN_ELEMS];        // q fp16 (scaled by 1/8), (b,l,d)
__device__ __half g_kh[IN_ELEMS];        // k*256 hi, (b,l,d)
__device__ __half g_kl[IN_ELEMS];        // k*256 lo
__device__ __half g_vh[IN_ELEMS];        // v*256 hi
__device__ __half g_vl[IN_ELEMS];        // v*256 lo
__device__ __half g_xh[OUT_ELEMS];       // AV output, fp16

// ================= helpers =================
__device__ __forceinline__ uint32_t smem_u32(const void* p){
    return (uint32_t)__cvta_generic_to_shared(p);
}
__device__ __forceinline__ void ldsm_x4(uint32_t* r, uint32_t addr){
    asm volatile("ldmatrix.sync.aligned.m8n8.x4.shared.b16 {%0,%1,%2,%3}, [%4];"
        : "=r"(r[0]),"=r"(r[1]),"=r"(r[2]),"=r"(r[3]) : "r"(addr));
}
__device__ __forceinline__ void ldsm_x4t(uint32_t* r, uint32_t addr){
    asm volatile("ldmatrix.sync.aligned.m8n8.x4.trans.shared.b16 {%0,%1,%2,%3}, [%4];"
        : "=r"(r[0]),"=r"(r[1]),"=r"(r[2]),"=r"(r[3]) : "r"(addr));
}
__device__ __forceinline__ void mma_f16(float* d, const uint32_t* a, const uint32_t* b){
    asm volatile("mma.sync.aligned.m16n8k16.row.col.f32.f16.f16.f32 "
        "{%0,%1,%2,%3}, {%4,%5,%6,%7}, {%8,%9}, {%0,%1,%2,%3};"
        : "+f"(d[0]),"+f"(d[1]),"+f"(d[2]),"+f"(d[3])
        : "r"(a[0]),"r"(a[1]),"r"(a[2]),"r"(a[3]), "r"(b[0]),"r"(b[1]));
}

// ---------------- 0a. round fp32 -> fp16 (3 inputs in one launch) ----------------
__global__ __launch_bounds__(256) void round_all(
    const float* __restrict__ q, const float* __restrict__ k,
    const float* __restrict__ v, __half* __restrict__ dst, int n4)
{
    int i = blockIdx.x * 256 + threadIdx.x;
    if (i >= n4) return;
    const float* src = (blockIdx.y == 0) ? q : ((blockIdx.y == 1) ? k : v);
    float4 f = ((const float4*)src)[i];
    __half2 h01 = __floats2half2_rn(f.x, f.y);
    __half2 h23 = __floats2half2_rn(f.z, f.w);
    *(uint2*)(dst + (size_t)blockIdx.y*IN_ELEMS + 4*(size_t)i) =
        make_uint2(*(uint32_t*)&h01, *(uint32_t*)&h23);
}

// ---------------- 0b. split (256*w) -> fp16 hi/lo, both weight mats ----------------
__global__ __launch_bounds__(256) void splitw_all(
    const float* __restrict__ ipw, const float* __restrict__ opw,
    __half* __restrict__ dh, __half* __restrict__ dl)
{
    int i = blockIdx.x * 256 + threadIdx.x;
    const int n4ip = 3*W_ELEMS/4;
    float4 f;
    if (i < n4ip) f = ((const float4*)ipw)[i];
    else          f = ((const float4*)opw)[i - n4ip];
    float sx = f.x*256.f, sy = f.y*256.f, sz = f.z*256.f, sw = f.w*256.f;
    __half2 h01 = __floats2half2_rn(sx, sy);
    __half2 h23 = __floats2half2_rn(sz, sw);
    __half2 l01 = __floats2half2_rn(sx - __half2float(h01.x), sy - __half2float(h01.y));
    __half2 l23 = __floats2half2_rn(sz - __half2float(h23.x), sw - __half2float(h23.y));
    *(uint2*)(dh + 4*(size_t)i) = make_uint2(*(uint32_t*)&h01, *(uint32_t*)&h23);
    *(uint2*)(dl + 4*(size_t)i) = make_uint2(*(uint32_t*)&l01, *(uint32_t*)&l23);
}

// ---- pipelined GEMM body: C(128x128) = A(128x768) * (Bh+Bl)(128x768)^T ----
__device__ __forceinline__ void gemm_body16(
    const __half* __restrict__ Ag, const __half* __restrict__ Bh,
    const __half* __restrict__ Bl,
    __half* sA, __half* sBh, __half* sBl,
    float acc[2][8][4], int tid)
{
    int lane = tid & 31, wid = tid >> 5;
    int wm = (wid & 3) * 32, wn = (wid >> 2) * 64;

    uint32_t aA = smem_u32(sA) + (uint32_t)((wm + (lane & 15))*80 + (lane >> 4)*16);
    int rowB = wn + (lane & 7) + ((lane >> 4) & 1)*8;
    uint32_t oBh = smem_u32(sBh) + (uint32_t)(rowB*80 + ((lane >> 3) & 1)*16);
    uint32_t oBl = smem_u32(sBl) + (uint32_t)(rowB*80 + ((lane >> 3) & 1)*16);

    int rr[2], ss[2];
    #pragma unroll
    for (int j = 0; j < 2; j++){
        int idx = j*256 + tid;
        rr[j] = idx >> 2;
        ss[j] = (idx & 3) * 8;
    }
    size_t go0 = (size_t)rr[0]*E_ + ss[0];
    size_t go1 = (size_t)rr[1]*E_ + ss[1];

    // preload chunk 0
    uint4 va[2], vh[2], vl[2];
    va[0] = *(const uint4*)(Ag + go0); va[1] = *(const uint4*)(Ag + go1);
    vh[0] = *(const uint4*)(Bh + go0); vh[1] = *(const uint4*)(Bh + go1);
    vl[0] = *(const uint4*)(Bl + go0); vl[1] = *(const uint4*)(Bl + go1);

    for (int ch = 0; ch < 24; ch++){
        __syncthreads();   // previous chunk fully consumed
        #pragma unroll
        for (int j = 0; j < 2; j++){
            int so = rr[j]*STRH + ss[j];
            *(uint4*)(sA  + so) = va[j];
            *(uint4*)(sBh + so) = vh[j];
            *(uint4*)(sBl + so) = vl[j];
        }
        __syncthreads();

        // issue next chunk loads before MMA (latency hidden behind MMA)
        if (ch + 1 < 24){
            int kB = (ch+1) * 32;
            va[0] = *(const uint4*)(Ag + go0 + kB); va[1] = *(const uint4*)(Ag + go1 + kB);
            vh[0] = *(const uint4*)(Bh + go0 + kB); vh[1] = *(const uint4*)(Bh + go1 + kB);
            vl[0] = *(const uint4*)(Bl + go0 + kB); vl[1] = *(const uint4*)(Bl + go1 + kB);
        }

        #pragma unroll
        for (int ks = 0; ks < 2; ks++){
            uint32_t a0[4], a1[4];
            ldsm_x4(a0, aA + ks*32);
            ldsm_x4(a1, aA + ks*32 + 16*80);
            #pragma unroll
            for (int q = 0; q < 4; q++){
                uint32_t bh[4], bl[4];
                ldsm_x4(bh, oBh + ks*32 + q*16*80);
                ldsm_x4(bl, oBl + ks*32 + q*16*80);
                mma_f16(acc[0][2*q],   a0, bh);
                mma_f16(acc[0][2*q+1], a0, bh+2);
                mma_f16(acc[0][2*q],   a0, bl);
                mma_f16(acc[0][2*q+1], a0, bl+2);
                mma_f16(acc[1][2*q],   a1, bh);
                mma_f16(acc[1][2*q+1], a1, bh+2);
                mma_f16(acc[1][2*q],   a1, bl);
                mma_f16(acc[1][2*q+1], a1, bl+2);
            }
        }
    }
}

// ---------------- 1. QKV projection; epilogue emits MMA-ready fp16 ----------------
__global__ __launch_bounds__(256, 2) void proj_tc(const float* __restrict__ bias)
{
    __shared__ __align__(16) __half sA[128*STRH], sBh[128*STRH], sBl[128*STRH];

    int tid = threadIdx.x, lane = tid & 31, wid = tid >> 5;
    int p = blockIdx.z;
    const __half* Ah = g_ah + (size_t)p*IN_ELEMS;
    const __half* Bh = g_wh + (size_t)p*W_ELEMS;
    const __half* Bl = g_wl + (size_t)p*W_ELEMS;
    const float* bp = bias + (size_t)p*E_;

    int l = blockIdx.y;
    int nBase = blockIdx.x * 128;
    size_t mBase = (size_t)l * 128;

    float acc[2][8][4];
    #pragma unroll
    for (int i=0;i<2;i++)
        #pragma unroll
        for (int j=0;j<8;j++)
            #pragma unroll
            for (int c=0;c<4;c++) acc[i][j][c] = 0.f;

    gemm_body16(Ah + mBase*E_, Bh + (size_t)nBase*E_, Bl + (size_t)nBase*E_,
                sA, sBh, sBl, acc, tid);

    int wm = (wid & 3) * 32, wn = (wid >> 2) * 64;
    #pragma unroll
    for (int mi = 0; mi < 2; mi++){
        int r = wm + mi*16 + (lane >> 2);
        #pragma unroll
        for (int ni = 0; ni < 8; ni++){
            int col = wn + ni*8 + (lane & 3)*2;
            int gc  = nBase + col;
            int h = gc >> 6, d = gc & 63;
            float b0 = bp[gc], b1 = bp[gc+1];
            float v00 = acc[mi][ni][0]*DESCALE + b0;
            float v01 = acc[mi][ni][1]*DESCALE + b1;
            float v10 = acc[mi][ni][2]*DESCALE + b0;
            float v11 = acc[mi][ni][3]*DESCALE + b1;
            size_t o0 = (((size_t)(r*H_ + h))*L_ + l)*HD_ + d;
            size_t o1 = (((size_t)((r+8)*H_ + h))*L_ + l)*HD_ + d;
            if (p == 0){
                __half2 q0 = __floats2half2_rn(v00*0.125f, v01*0.125f);
                __half2 q1 = __floats2half2_rn(v10*0.125f, v11*0.125f);
                *(uint32_t*)&g_qh[o0] = *(uint32_t*)&q0;
                *(uint32_t*)&g_qh[o1] = *(uint32_t*)&q1;
            } else {
                __half* dsth = (p == 1) ? g_kh : g_vh;
                __half* dstl = (p == 1) ? g_kl : g_vl;
                float s00 = v00*256.f, s01 = v01*256.f, s10 = v10*256.f, s11 = v11*256.f;
                __half2 h0 = __floats2half2_rn(s00, s01);
                __half2 h1 = __floats2half2_rn(s10, s11);
                __half2 l0 = __floats2half2_rn(s00 - __half2float(h0.x), s01 - __half2float(h0.y));
                __half2 l1 = __floats2half2_rn(s10 - __half2float(h1.x), s11 - __half2float(h1.y));
                *(uint32_t*)&dsth[o0] = *(uint32_t*)&h0;
                *(uint32_t*)&dsth[o1] = *(uint32_t*)&h1;
                *(uint32_t*)&dstl[o0] = *(uint32_t*)&l0;
                *(uint32_t*)&dstl[o1] = *(uint32_t*)&l1;
            }
        }
    }
}

// ---------------- 6. out projection ----------------
__global__ __launch_bounds__(256, 2) void out_tc(
    const float* __restrict__ bias, float* __restrict__ outp)
{
    __shared__ __align__(16) __half sA[128*STRH], sBh[128*STRH], sBl[128*STRH];

    int tid = threadIdx.x, lane = tid & 31, wid = tid >> 5;
    size_t mBase = (size_t)blockIdx.y * 128;
    int nBase = blockIdx.x * 128;

    float acc[2][8][4];
    #pragma unroll
    for (int i=0;i<2;i++)
        #pragma unroll
        for (int j=0;j<8;j++)
            #pragma unroll
            for (int c=0;c<4;c++) acc[i][j][c] = 0.f;

    gemm_body16(g_xh + mBase*E_,
                g_wh + (size_t)3*W_ELEMS + (size_t)nBase*E_,
                g_wl + (size_t)3*W_ELEMS + (size_t)nBase*E_,
                sA, sBh, sBl, acc, tid);

    int wm = (wid & 3) * 32, wn = (wid >> 2) * 64;
    #pragma unroll
    for (int mi = 0; mi < 2; mi++){
        int r = wm + mi*16 + (lane >> 2);
        #pragma unroll
        for (int ni = 0; ni < 8; ni++){
            int col = wn + ni*8 + (lane & 3)*2;
            int gc  = nBase + col;
            float b0 = bias[gc], b1 = bias[gc+1];
            float2 v0 = make_float2(acc[mi][ni][0]*DESCALE + b0,
                                    acc[mi][ni][1]*DESCALE + b1);
            float2 v1 = make_float2(acc[mi][ni][2]*DESCALE + b0,
                                    acc[mi][ni][3]*DESCALE + b1);
            *(float2*)&outp[(mBase + r)*E_ + gc] = v0;
            *(float2*)&outp[(mBase + r + 8)*E_ + gc] = v1;
        }
    }
}

// ---------------- 2. QK^T (pipelined, raw fp32 scores to concat slots) ----------------
__global__ __launch_bounds__(256, 2) void qk_mma()
{
    __shared__ __align__(16) __half Qs[64*STR2];
    __shared__ __align__(16) __half Kh[64*STR2], Kl[64*STR2];

    int b = blockIdx.x, tt = blockIdx.y;
    int tid = threadIdx.x, lane = tid & 31, wid = tid >> 5;
    const __half* qb  = g_qh + (size_t)b*L_*HD_;
    const __half* kbh = g_kh + (size_t)b*L_*HD_;
    const __half* kbl = g_kl + (size_t)b*L_*HD_;

    const uint4 z4 = make_uint4(0,0,0,0);
    #pragma unroll
    for (int i = 0; i < 2; i++){
        int idx = i*256 + tid;
        int r = idx >> 3, c8 = (idx & 7) * 8;
        int tg = tt*64 + r;
        uint4 v = z4;
        if (tg < L_) v = *(const uint4*)&qb[(size_t)tg*HD_ + c8];
        *(uint4*)(Qs + r*STR2 + c8) = v;
    }

    int wm = (wid & 3) * 16, wn = (wid >> 2) * 32;
    uint32_t aQ = smem_u32(Qs) + (uint32_t)((wm + (lane & 15))*144 + (lane >> 4)*16);
    int rowB = wn + (lane & 7) + ((lane >> 4) & 1)*8;
    uint32_t aKh = smem_u32(Kh) + (uint32_t)(rowB*144 + ((lane >> 3) & 1)*16);
    uint32_t aKl = smem_u32(Kl) + (uint32_t)(rowB*144 + ((lane >> 3) & 1)*16);

    int rr[2], cc8[2];
    #pragma unroll
    for (int i = 0; i < 2; i++){
        int idx = i*256 + tid;
        rr[i] = idx >> 3; cc8[i] = (idx & 7) * 8;
    }

    // preload K chunk ts=0
    uint4 pvh[2], pvl[2];
    #pragma unroll
    for (int i = 0; i < 2; i++){
        int sg = rr[i];
        pvh[i] = z4; pvl[i] = z4;
        if (sg < L_){
            pvh[i] = *(const uint4*)&kbh[(size_t)sg*HD_ + cc8[i]];
            pvl[i] = *(const uint4*)&kbl[(size_t)sg*HD_ + cc8[i]];
        }
    }

    for (int ts = 0; ts < 4; ts++){
        __syncthreads();
        #pragma unroll
        for (int i = 0; i < 2; i++){
            *(uint4*)(Kh + rr[i]*STR2 + cc8[i]) = pvh[i];
            *(uint4*)(Kl + rr[i]*STR2 + cc8[i]) = pvl[i];
        }
        __syncthreads();

        if (ts + 1 < 4){
            #pragma unroll
            for (int i = 0; i < 2; i++){
                int sg = (ts+1)*64 + rr[i];
                pvh[i] = z4; pvl[i] = z4;
                if (sg < L_){
                    pvh[i] = *(const uint4*)&kbh[(size_t)sg*HD_ + cc8[i]];
                    pvl[i] = *(const uint4*)&kbl[(size_t)sg*HD_ + cc8[i]];
                }
            }
        }

        float acc[4][4];
        #pragma unroll
        for (int i=0;i<4;i++)
            #pragma unroll
            for (int j=0;j<4;j++) acc[i][j] = 0.f;

        #pragma unroll
        for (int ks = 0; ks < 4; ks++){
            uint32_t a[4];
            ldsm_x4(a, aQ + ks*32);
            #pragma unroll
            for (int q = 0; q < 2; q++){
                uint32_t bh[4], bl[4];
                ldsm_x4(bh, aKh + ks*32 + q*16*144);
                ldsm_x4(bl, aKl + ks*32 + q*16*144);
                mma_f16(acc[2*q],   a, bh);
                mma_f16(acc[2*q+1], a, bh+2);
                mma_f16(acc[2*q],   a, bl);
                mma_f16(acc[2*q+1], a, bl+2);
            }
        }

        int t0 = tt*64 + wm + (lane >> 2);
        int t1 = t0 + 8;
        #pragma unroll
        for (int ni = 0; ni < 4; ni++){
            int s = ts*64 + wn + ni*8 + (lane & 3)*2;
            if (s >= L_) continue;
            bool two = (s + 1 < L_);
            if (t0 < L_){
                int slot = (t0==0) ? 0 : (t0 + NS_);
                float* dst = &g_attn[((size_t)b*LT_ + slot)*LP_ + s];
                if (two) *(float2*)dst = make_float2(acc[ni][0]*DESCALE, acc[ni][1]*DESCALE);
                else     dst[0] = acc[ni][0]*DESCALE;
            }
            if (t1 < L_){
                int slot = (t1==0) ? 0 : (t1 + NS_);
                float* dst = &g_attn[((size_t)b*LT_ + slot)*LP_ + s];
                if (two) *(float2*)dst = make_float2(acc[ni][2]*DESCALE, acc[ni][3]*DESCALE);
                else     dst[0] = acc[ni][2]*DESCALE;
            }
        }
    }
}

// ---------------- 5. AV -> fp16 X (pipelined; probs fp16, V via ldmatrix.trans) -------
__global__ __launch_bounds__(256, 2) void av_mma()
{
    __shared__ __align__(16) __half Ahs[64*STR2];
    __shared__ __align__(16) __half Vh[64*STR2], Vl[64*STR2];   // [s][d] row-major

    int b = blockIdx.x, tT = blockIdx.y;
    int tid = threadIdx.x, lane = tid & 31, wid = tid >> 5;
    const __half* attn_b = g_p16 + (size_t)b*LT_*LP_;
    const __half* vbh = g_vh + (size_t)b*L_*HD_;
    const __half* vbl = g_vl + (size_t)b*L_*HD_;

    int wm = (wid & 3) * 16, wn = (wid >> 2) * 32;
    uint32_t aA = smem_u32(Ahs) + (uint32_t)((wm + (lane & 15))*144 + (lane >> 4)*16);
    uint32_t aVh = smem_u32(Vh) + (uint32_t)((lane & 15)*144 + (wn + (lane >> 4)*8)*2);
    uint32_t aVl = smem_u32(Vl) + (uint32_t)((lane & 15)*144 + (wn + (lane >> 4)*8)*2);

    float acc[4][4];
    #pragma unroll
    for (int i=0;i<4;i++)
        #pragma unroll
        for (int j=0;j<4;j++) acc[i][j] = 0.f;

    const uint4 z4 = make_uint4(0,0,0,0);
    int rr[2], cc8[2];
    #pragma unroll
    for (int i = 0; i < 2; i++){
        int idx = i*256 + tid;
        rr[i] = idx >> 3; cc8[i] = (idx & 7) * 8;
    }

    // preload chunk s0=0
    uint4 pa[2], pvh[2], pvl[2];
    #pragma unroll
    for (int i = 0; i < 2; i++){
        int t = tT*64 + rr[i];
        pa[i] = z4;
        if (t < LT_ && cc8[i] + 8 <= LP_)
            pa[i] = *(const uint4*)&attn_b[(size_t)t*LP_ + cc8[i]];
        int sv = rr[i];
        pvh[i] = z4; pvl[i] = z4;
        if (sv < L_){
            pvh[i] = *(const uint4*)&vbh[(size_t)sv*HD_ + cc8[i]];
            pvl[i] = *(const uint4*)&vbl[(size_t)sv*HD_ + cc8[i]];
        }
    }

    for (int s0 = 0; s0 < L_; s0 += 64){
        __syncthreads();
        #pragma unroll
        for (int i = 0; i < 2; i++){
            *(uint4*)(Ahs + rr[i]*STR2 + cc8[i]) = pa[i];
            *(uint4*)(Vh  + rr[i]*STR2 + cc8[i]) = pvh[i];
            *(uint4*)(Vl  + rr[i]*STR2 + cc8[i]) = pvl[i];
        }
        __syncthreads();

        int s1 = s0 + 64;
        if (s1 < L_){
            #pragma unroll
            for (int i = 0; i < 2; i++){
                int t = tT*64 + rr[i];
                int s = s1 + cc8[i];
                pa[i] = z4;
                if (t < LT_ && s + 8 <= LP_)
                    pa[i] = *(const uint4*)&attn_b[(size_t)t*LP_ + s];
                int sv = s1 + rr[i];
                pvh[i] = z4; pvl[i] = z4;
                if (sv < L_){
                    pvh[i] = *(const uint4*)&vbh[(size_t)sv*HD_ + cc8[i]];
                    pvl[i] = *(const uint4*)&vbl[(size_t)sv*HD_ + cc8[i]];
                }
            }
        }

        #pragma unroll
        for (int ks = 0; ks < 4; ks++){
            uint32_t a[4];
            ldsm_x4(a, aA + ks*32);
            #pragma unroll
            for (int q = 0; q < 2; q++){
                uint32_t bh[4], bl[4];
                ldsm_x4t(bh, aVh + ks*16*144 + q*32);
                ldsm_x4t(bl, aVl + ks*16*144 + q*32);
                mma_f16(acc[2*q],   a, bh);
                mma_f16(acc[2*q+1], a, bh+2);
                mma_f16(acc[2*q],   a, bl);
                mma_f16(acc[2*q+1], a, bl+2);
            }
        }
    }

    int n = b / H_, h = b % H_;
    int t0 = tT*64 + wm + (lane >> 2);
    int t1 = t0 + 8;
    #pragma unroll
    for (int ni = 0; ni < 4; ni++){
        int d = wn + ni*8 + (lane & 3)*2;
        #pragma unroll
        for (int half = 0; half < 2; half++){
            int t = half ? t1 : t0;
            if (t >= LT_) continue;
            __half2 hh = __floats2half2_rn(acc[ni][half*2]*DESCALE,
                                           acc[ni][half*2+1]*DESCALE);
            *(uint32_t*)&g_xh[((size_t)t*NB_ + n)*E_ + h*HD_ + d] = *(uint32_t*)&hh;
        }
    }
}

// ---------------- threefry2x32 (bit-exact JAX, partitionable) ----------------
__device__ __forceinline__ uint32_t rotl32(uint32_t x, int r){ return (x<<r)|(x>>(32-r)); }

__device__ __forceinline__ void tf2x32(uint32_t k0, uint32_t k1, uint32_t x0, uint32_t x1,
                                       uint32_t &o0, uint32_t &o1)
{
    uint32_t ks2 = k0 ^ k1 ^ 0x1BD11BDAu;
#define TFR(r) { x0 += x1; x1 = rotl32(x1, (r)); x1 ^= x0; }
    x0 += k0; x1 += k1;
    TFR(13) TFR(15) TFR(26) TFR(6)
    x0 += k1;  x1 += ks2 + 1u;
    TFR(17) TFR(29) TFR(16) TFR(24)
    x0 += ks2; x1 += k0 + 2u;
    TFR(13) TFR(15) TFR(26) TFR(6)
    x0 += k0;  x1 += k1 + 3u;
    TFR(17) TFR(29) TFR(16) TFR(24)
    x0 += k1;  x1 += ks2 + 4u;
    TFR(13) TFR(15) TFR(26) TFR(6)
    x0 += ks2; x1 += k0 + 5u;
#undef TFR
    o0 = x0; o1 = x1;
}

__device__ __forceinline__ uint32_t rbits32(uint32_t ka, uint32_t kb, uint32_t i){
    uint32_t o0, o1;
    tf2x32(ka, kb, 0u, i, o0, o1);
    return o0 ^ o1;
}

__device__ __forceinline__ float u01(uint32_t bits){
    return __uint_as_float((bits >> 9) | 0x3f800000u) - 1.0f;
}

__device__ __forceinline__ float blockSum256(float v, float* red){
    #pragma unroll
    for (int o=16;o>0;o>>=1) v += __shfl_xor_sync(0xffffffffu, v, o);
    __syncthreads();
    if ((threadIdx.x & 31) == 0) red[threadIdx.x >> 5] = v;
    __syncthreads();
    float s = red[0];
    #pragma unroll
    for (int i=1;i<8;i++) s += red[i];
    return s;
}

__device__ __forceinline__ float warpSum(float v){
    #pragma unroll
    for (int o=16;o>0;o>>=1) v += __shfl_xor_sync(0xffffffffu, v, o);
    return v;
}

// ---------------- 3. random rows: warp-per-sample, fused softmax -> fp16 probs ------
__global__ __launch_bounds__(256) void rand_kernel()
{
    int b   = blockIdx.x;
    int tid = threadIdx.x, lid = tid & 31, wid = tid >> 5;
    __shared__ float u[L_];
    __shared__ float red[8];
    __shared__ float norm_sh;

    uint32_t k1a, k1b, k2a, k2b;
    tf2x32(0u, 1234u, 0u, 0u, k1a, k1b);
    tf2x32(0u, 1234u, 0u, 1u, k2a, k2b);

    float c = 0.f;
    if (tid < L_) c = g_attn[(size_t)b*LT_*LP_ + tid];   // raw center row
    float ss = blockSum256(c*c, red);
    if (tid == 0) norm_sh = sqrtf(ss);
    __syncthreads();
    float norm = norm_sh;
    float nden = fmaxf(norm, 1e-12f);
    if (tid < L_) u[tid] = c / nden;
    __syncthreads();

    for (int n = wid; n < NS_; n += 8){
        float fc = u01(rbits32(k2a, k2b, (uint32_t)n));
        float cosn = fc * 0.2f + 0.7f;
        float sinn = sqrtf(1.0f - cosn*cosn);

        float r[7], uu[7];
        float dot = 0.f;
        uint32_t base = ((uint32_t)n*1536u + (uint32_t)b)*197u;
        #pragma unroll
        for (int i = 0; i < 7; i++){
            int idx = i*32 + lid;
            if (idx < L_){
                r[i]  = u01(rbits32(k1a, k1b, base + (uint32_t)idx)) * 2.0f - 1.0f;
                uu[i] = u[idx];
            } else { r[i] = 0.f; uu[i] = 0.f; }
            dot += r[i]*uu[i];
        }
        dot = warpSum(dot);
        float tsum = 0.f;
        #pragma unroll
        for (int i = 0; i < 7; i++){
            r[i] = r[i] - dot*uu[i];
            tsum += r[i]*r[i];
        }
        tsum = warpSum(tsum);
        float inv = 1.0f / fmaxf(sqrtf(tsum), 1e-12f);

        float w[7];
        float m = -3.402823466e38f;
        #pragma unroll
        for (int i = 0; i < 7; i++){
            int idx = i*32 + lid;
            w[i] = (idx < L_) ? (cosn*uu[i] + sinn*(r[i]*inv)) * norm
                              : -3.402823466e38f;
            m = fmaxf(m, w[i]);
        }
        #pragma unroll
        for (int o=16;o>0;o>>=1) m = fmaxf(m, __shfl_xor_sync(0xffffffffu, m, o));
        float s = 0.f;
        #pragma unroll
        for (int i = 0; i < 7; i++){
            w[i] = expf(w[i] - m);
            s += w[i];
        }
        s = warpSum(s);
        float sinv = 1.0f / s;

        __half* dst = &g_p16[((size_t)b*LT_ + 1 + n)*LP_];
        #pragma unroll
        for (int i = 0; i < 7; i++){
            int idx = i*32 + lid;
            if (idx < L_) dst[idx] = __float2half_rn(w[i] * sinv);
            else if (idx < LP_) dst[idx] = __ushort_as_half((unsigned short)0);
        }
    }
}

// ---------------- 4. softmax: fp32 raw -> fp16 probs, only the 197 qk rows ----------
__global__ __launch_bounds__(256) void softmax_kernel()
{
    int wid = threadIdx.x >> 5, lid = threadIdx.x & 31;
    int g = blockIdx.x * 8 + wid;
    int b  = g / 200;
    int ri = g % 200;
    if (ri >= L_) return;
    int slot = (ri == 0) ? 0 : (ri + NS_);
    const float* p = g_attn + ((size_t)b*LT_ + slot) * LP_;
    __half* po = g_p16 + ((size_t)b*LT_ + slot) * LP_;

    float v[7];
    float m = -3.402823466e38f;
    #pragma unroll
    for (int i = 0; i < 7; i++){
        int idx = i*32 + lid;
        v[i] = (idx < L_) ? p[idx] : -3.402823466e38f;
        m = fmaxf(m, v[i]);
    }
    #pragma unroll
    for (int o=16;o>0;o>>=1) m = fmaxf(m, __shfl_xor_sync(0xffffffffu, m, o));
    float s = 0.f;
    #pragma unroll
    for (int i = 0; i < 7; i++){
        v[i] = expf(v[i] - m);
        s += v[i];
    }
    #pragma unroll
    for (int o=16;o>0;o>>=1) s += __shfl_xor_sync(0xffffffffu, s, o);
    float inv = 1.0f / s;
    #pragma unroll
    for (int i = 0; i < 7; i++){
        int idx = i*32 + lid;
        if (idx < L_) po[idx] = __float2half_rn(v[i] * inv);
        else if (idx < LP_) po[idx] = __ushort_as_half((unsigned short)0);
    }
}

// ---------------- 7. attn_weights = mean over heads (fp16 probs) ----------------
__global__ __launch_bounds__(256) void mean_kernel(float* __restrict__ aw)
{
    int idx = blockIdx.x * 256 + threadIdx.x;
    if (idx >= AW_ELEMS) return;
    int s = idx % L_;
    int t = (idx / L_) % LT_;
    int n = idx / (L_ * LT_);
    float sum = 0.f;
    #pragma unroll
    for (int h=0; h<H_; h++)
        sum += __half2float(g_p16[(((size_t)(n*H_ + h))*LT_ + t)*LP_ + s]);
    aw[idx] = sum * (1.0f/12.0f);
}

// ---------------- launch ----------------
extern "C" void kernel_launch(void* const* d_in, const int* in_sizes, int n_in,
                              void* d_out, int out_size)
{
    const float* q   = (const float*)d_in[0];
    const float* k   = (const float*)d_in[1];
    const float* v   = (const float*)d_in[2];
    const float* ipw = (const float*)d_in[3];
    const float* ipb = (const float*)d_in[4];
    const float* opw = (const float*)d_in[5];
    const float* opb = (const float*)d_in[6];
    float* out = (float*)d_out;

    __half *ah, *wh, *wl;
    cudaGetSymbolAddress((void**)&ah, g_ah);
    cudaGetSymbolAddress((void**)&wh, g_wh);
    cudaGetSymbolAddress((void**)&wl, g_wl);

    const int n4in = IN_ELEMS/4;
    round_all<<<dim3((n4in+255)/256, 3), 256>>>(q, k, v, ah, n4in);
    splitw_all<<<(4*W_ELEMS/4+255)/256, 256>>>(ipw, opw, wh, wl);

    proj_tc<<<dim3(6,197,3), 256>>>(ipb);
    qk_mma<<<dim3(1536,4), 256>>>();
    rand_kernel<<<1536, 256>>>();
    softmax_kernel<<<(B_*200)/8, 256>>>();
    av_mma<<<dim3(1536,5), 256>>>();
    out_tc<<<dim3(6,257), 256>>>(opb, out);
    mean_kernel<<<(AW_ELEMS + 255)/256, 256>>>(out + OUT_ELEMS);
}

// round 16
// speedup vs baseline: 1.0105x; 1.0105x over previous
#include <cuda_runtime.h>
#include <cuda_fp16.h>
#include <cstdint>

#define L_   197
#define LP_  200
#define NB_  128
#define E_   768
#define H_   12
#define HD_  64
#define B_   1536
#define NS_  60
#define LT_  257
#define OUT_ELEMS 25264128
#define AW_ELEMS  6480512

#define STRH 40        // proj/out smem row stride in halves (80 B)
#define STR2 72        // qk/av smem row stride in halves (144 B)

#define IN_ELEMS 19365888        // 25216*768
#define W_ELEMS  589824          // 768*768
#define DESCALE 0.00390625f      // 2^-8
#define NEG_INF -3.402823466e38f

// ---------------- scratch ----------------
__device__ float  g_attn[78950400];      // (B, LT, LP_) raw center rows only
__device__ __half g_p16[78950400];       // (B, LT, LP_) post-softmax probs (fp16)
__device__ __half g_ah[3*IN_ELEMS];      // inputs rounded to fp16 (proj A)
__device__ __half g_wh[4*W_ELEMS];       // weights*256 hi
__device__ __half g_wl[4*W_ELEMS];       // weights*256 lo
__device__ __half g_qh[IN_ELEMS];        // q fp16 (scaled by 1/8), (b,l,d)
__device__ __half g_kh[IN_ELEMS];        // k*256 hi, (b,l,d)
__device__ __half g_kl[IN_ELEMS];        // k*256 lo
__device__ __half g_vh[IN_ELEMS];        // v*256 hi
__device__ __half g_vl[IN_ELEMS];        // v*256 lo
__device__ __half g_xh[OUT_ELEMS];       // AV output, fp16

// ================= helpers =================
__device__ __forceinline__ uint32_t smem_u32(const void* p){
    return (uint32_t)__cvta_generic_to_shared(p);
}
__device__ __forceinline__ void ldsm_x4(uint32_t* r, uint32_t addr){
    asm volatile("ldmatrix.sync.aligned.m8n8.x4.shared.b16 {%0,%1,%2,%3}, [%4];"
        : "=r"(r[0]),"=r"(r[1]),"=r"(r[2]),"=r"(r[3]) : "r"(addr));
}
__device__ __forceinline__ void ldsm_x4t(uint32_t* r, uint32_t addr){
    asm volatile("ldmatrix.sync.aligned.m8n8.x4.trans.shared.b16 {%0,%1,%2,%3}, [%4];"
        : "=r"(r[0]),"=r"(r[1]),"=r"(r[2]),"=r"(r[3]) : "r"(addr));
}
__device__ __forceinline__ void mma_f16(float* d, const uint32_t* a, const uint32_t* b){
    asm volatile("mma.sync.aligned.m16n8k16.row.col.f32.f16.f16.f32 "
        "{%0,%1,%2,%3}, {%4,%5,%6,%7}, {%8,%9}, {%0,%1,%2,%3};"
        : "+f"(d[0]),"+f"(d[1]),"+f"(d[2]),"+f"(d[3])
        : "r"(a[0]),"r"(a[1]),"r"(a[2]),"r"(a[3]), "r"(b[0]),"r"(b[1]));
}

// ---------------- 0a. round fp32 -> fp16 (3 inputs in one launch) ----------------
__global__ __launch_bounds__(256) void round_all(
    const float* __restrict__ q, const float* __restrict__ k,
    const float* __restrict__ v, __half* __restrict__ dst, int n4)
{
    int i = blockIdx.x * 256 + threadIdx.x;
    if (i >= n4) return;
    const float* src = (blockIdx.y == 0) ? q : ((blockIdx.y == 1) ? k : v);
    float4 f = ((const float4*)src)[i];
    __half2 h01 = __floats2half2_rn(f.x, f.y);
    __half2 h23 = __floats2half2_rn(f.z, f.w);
    *(uint2*)(dst + (size_t)blockIdx.y*IN_ELEMS + 4*(size_t)i) =
        make_uint2(*(uint32_t*)&h01, *(uint32_t*)&h23);
}

// ---------------- 0b. split (256*w) -> fp16 hi/lo, both weight mats ----------------
__global__ __launch_bounds__(256) void splitw_all(
    const float* __restrict__ ipw, const float* __restrict__ opw,
    __half* __restrict__ dh, __half* __restrict__ dl)
{
    int i = blockIdx.x * 256 + threadIdx.x;
    const int n4ip = 3*W_ELEMS/4;
    float4 f;
    if (i < n4ip) f = ((const float4*)ipw)[i];
    else          f = ((const float4*)opw)[i - n4ip];
    float sx = f.x*256.f, sy = f.y*256.f, sz = f.z*256.f, sw = f.w*256.f;
    __half2 h01 = __floats2half2_rn(sx, sy);
    __half2 h23 = __floats2half2_rn(sz, sw);
    __half2 l01 = __floats2half2_rn(sx - __half2float(h01.x), sy - __half2float(h01.y));
    __half2 l23 = __floats2half2_rn(sz - __half2float(h23.x), sw - __half2float(h23.y));
    *(uint2*)(dh + 4*(size_t)i) = make_uint2(*(uint32_t*)&h01, *(uint32_t*)&h23);
    *(uint2*)(dl + 4*(size_t)i) = make_uint2(*(uint32_t*)&l01, *(uint32_t*)&l23);
}

// ---- pipelined GEMM body: C(128x128) = A(128x768) * (Bh+Bl)(128x768)^T ----
__device__ __forceinline__ void gemm_body16(
    const __half* __restrict__ Ag, const __half* __restrict__ Bh,
    const __half* __restrict__ Bl,
    __half* sA, __half* sBh, __half* sBl,
    float acc[2][8][4], int tid)
{
    int lane = tid & 31, wid = tid >> 5;
    int wm = (wid & 3) * 32, wn = (wid >> 2) * 64;

    uint32_t aA = smem_u32(sA) + (uint32_t)((wm + (lane & 15))*80 + (lane >> 4)*16);
    int rowB = wn + (lane & 7) + ((lane >> 4) & 1)*8;
    uint32_t oBh = smem_u32(sBh) + (uint32_t)(rowB*80 + ((lane >> 3) & 1)*16);
    uint32_t oBl = smem_u32(sBl) + (uint32_t)(rowB*80 + ((lane >> 3) & 1)*16);

    int rr[2], ss[2];
    #pragma unroll
    for (int j = 0; j < 2; j++){
        int idx = j*256 + tid;
        rr[j] = idx >> 2;
        ss[j] = (idx & 3) * 8;
    }
    size_t go0 = (size_t)rr[0]*E_ + ss[0];
    size_t go1 = (size_t)rr[1]*E_ + ss[1];

    uint4 va[2], vh[2], vl[2];
    va[0] = *(const uint4*)(Ag + go0); va[1] = *(const uint4*)(Ag + go1);
    vh[0] = *(const uint4*)(Bh + go0); vh[1] = *(const uint4*)(Bh + go1);
    vl[0] = *(const uint4*)(Bl + go0); vl[1] = *(const uint4*)(Bl + go1);

    for (int ch = 0; ch < 24; ch++){
        __syncthreads();
        #pragma unroll
        for (int j = 0; j < 2; j++){
            int so = rr[j]*STRH + ss[j];
            *(uint4*)(sA  + so) = va[j];
            *(uint4*)(sBh + so) = vh[j];
            *(uint4*)(sBl + so) = vl[j];
        }
        __syncthreads();

        if (ch + 1 < 24){
            int kB = (ch+1) * 32;
            va[0] = *(const uint4*)(Ag + go0 + kB); va[1] = *(const uint4*)(Ag + go1 + kB);
            vh[0] = *(const uint4*)(Bh + go0 + kB); vh[1] = *(const uint4*)(Bh + go1 + kB);
            vl[0] = *(const uint4*)(Bl + go0 + kB); vl[1] = *(const uint4*)(Bl + go1 + kB);
        }

        #pragma unroll
        for (int ks = 0; ks < 2; ks++){
            uint32_t a0[4], a1[4];
            ldsm_x4(a0, aA + ks*32);
            ldsm_x4(a1, aA + ks*32 + 16*80);
            #pragma unroll
            for (int q = 0; q < 4; q++){
                uint32_t bh[4], bl[4];
                ldsm_x4(bh, oBh + ks*32 + q*16*80);
                ldsm_x4(bl, oBl + ks*32 + q*16*80);
                mma_f16(acc[0][2*q],   a0, bh);
                mma_f16(acc[0][2*q+1], a0, bh+2);
                mma_f16(acc[0][2*q],   a0, bl);
                mma_f16(acc[0][2*q+1], a0, bl+2);
                mma_f16(acc[1][2*q],   a1, bh);
                mma_f16(acc[1][2*q+1], a1, bh+2);
                mma_f16(acc[1][2*q],   a1, bl);
                mma_f16(acc[1][2*q+1], a1, bl+2);
            }
        }
    }
}

// ---------------- 1. QKV projection; epilogue emits MMA-ready fp16 ----------------
__global__ __launch_bounds__(256, 2) void proj_tc(const float* __restrict__ bias)
{
    __shared__ __align__(16) __half sA[128*STRH], sBh[128*STRH], sBl[128*STRH];

    int tid = threadIdx.x, lane = tid & 31, wid = tid >> 5;
    int p = blockIdx.z;
    const __half* Ah = g_ah + (size_t)p*IN_ELEMS;
    const __half* Bh = g_wh + (size_t)p*W_ELEMS;
    const __half* Bl = g_wl + (size_t)p*W_ELEMS;
    const float* bp = bias + (size_t)p*E_;

    int l = blockIdx.y;
    int nBase = blockIdx.x * 128;
    size_t mBase = (size_t)l * 128;

    float acc[2][8][4];
    #pragma unroll
    for (int i=0;i<2;i++)
        #pragma unroll
        for (int j=0;j<8;j++)
            #pragma unroll
            for (int c=0;c<4;c++) acc[i][j][c] = 0.f;

    gemm_body16(Ah + mBase*E_, Bh + (size_t)nBase*E_, Bl + (size_t)nBase*E_,
                sA, sBh, sBl, acc, tid);

    int wm = (wid & 3) * 32, wn = (wid >> 2) * 64;
    #pragma unroll
    for (int mi = 0; mi < 2; mi++){
        int r = wm + mi*16 + (lane >> 2);
        #pragma unroll
        for (int ni = 0; ni < 8; ni++){
            int col = wn + ni*8 + (lane & 3)*2;
            int gc  = nBase + col;
            int h = gc >> 6, d = gc & 63;
            float b0 = bp[gc], b1 = bp[gc+1];
            float v00 = acc[mi][ni][0]*DESCALE + b0;
            float v01 = acc[mi][ni][1]*DESCALE + b1;
            float v10 = acc[mi][ni][2]*DESCALE + b0;
            float v11 = acc[mi][ni][3]*DESCALE + b1;
            size_t o0 = (((size_t)(r*H_ + h))*L_ + l)*HD_ + d;
            size_t o1 = (((size_t)((r+8)*H_ + h))*L_ + l)*HD_ + d;
            if (p == 0){
                __half2 q0 = __floats2half2_rn(v00*0.125f, v01*0.125f);
                __half2 q1 = __floats2half2_rn(v10*0.125f, v11*0.125f);
                *(uint32_t*)&g_qh[o0] = *(uint32_t*)&q0;
                *(uint32_t*)&g_qh[o1] = *(uint32_t*)&q1;
            } else {
                __half* dsth = (p == 1) ? g_kh : g_vh;
                __half* dstl = (p == 1) ? g_kl : g_vl;
                float s00 = v00*256.f, s01 = v01*256.f, s10 = v10*256.f, s11 = v11*256.f;
                __half2 h0 = __floats2half2_rn(s00, s01);
                __half2 h1 = __floats2half2_rn(s10, s11);
                __half2 l0 = __floats2half2_rn(s00 - __half2float(h0.x), s01 - __half2float(h0.y));
                __half2 l1 = __floats2half2_rn(s10 - __half2float(h1.x), s11 - __half2float(h1.y));
                *(uint32_t*)&dsth[o0] = *(uint32_t*)&h0;
                *(uint32_t*)&dsth[o1] = *(uint32_t*)&h1;
                *(uint32_t*)&dstl[o0] = *(uint32_t*)&l0;
                *(uint32_t*)&dstl[o1] = *(uint32_t*)&l1;
            }
        }
    }
}

// ---------------- 6. out projection ----------------
__global__ __launch_bounds__(256, 2) void out_tc(
    const float* __restrict__ bias, float* __restrict__ outp)
{
    __shared__ __align__(16) __half sA[128*STRH], sBh[128*STRH], sBl[128*STRH];

    int tid = threadIdx.x, lane = tid & 31, wid = tid >> 5;
    size_t mBase = (size_t)blockIdx.y * 128;
    int nBase = blockIdx.x * 128;

    float acc[2][8][4];
    #pragma unroll
    for (int i=0;i<2;i++)
        #pragma unroll
        for (int j=0;j<8;j++)
            #pragma unroll
            for (int c=0;c<4;c++) acc[i][j][c] = 0.f;

    gemm_body16(g_xh + mBase*E_,
                g_wh + (size_t)3*W_ELEMS + (size_t)nBase*E_,
                g_wl + (size_t)3*W_ELEMS + (size_t)nBase*E_,
                sA, sBh, sBl, acc, tid);

    int wm = (wid & 3) * 32, wn = (wid >> 2) * 64;
    #pragma unroll
    for (int mi = 0; mi < 2; mi++){
        int r = wm + mi*16 + (lane >> 2);
        #pragma unroll
        for (int ni = 0; ni < 8; ni++){
            int col = wn + ni*8 + (lane & 3)*2;
            int gc  = nBase + col;
            float b0 = bias[gc], b1 = bias[gc+1];
            float2 v0 = make_float2(acc[mi][ni][0]*DESCALE + b0,
                                    acc[mi][ni][1]*DESCALE + b1);
            float2 v1 = make_float2(acc[mi][ni][2]*DESCALE + b0,
                                    acc[mi][ni][3]*DESCALE + b1);
            *(float2*)&outp[(mBase + r)*E_ + gc] = v0;
            *(float2*)&outp[(mBase + r + 8)*E_ + gc] = v1;
        }
    }
}

// ---------------- 2. QK^T with register-resident FUSED SOFTMAX -> fp16 probs --------
__global__ __launch_bounds__(256) void qk_mma()
{
    __shared__ __align__(16) __half Qs[64*STR2];
    __shared__ __align__(16) __half Kh[64*STR2], Kl[64*STR2];
    __shared__ float xch[8][16];

    int b = blockIdx.x, tt = blockIdx.y;
    int tid = threadIdx.x, lane = tid & 31, wid = tid >> 5;
    const __half* qb  = g_qh + (size_t)b*L_*HD_;
    const __half* kbh = g_kh + (size_t)b*L_*HD_;
    const __half* kbl = g_kl + (size_t)b*L_*HD_;

    // zero pad cols 197..199 of this CTA's prob rows
    if (tid < 64){
        int t = tt*64 + tid;
        if (t < L_){
            int slot = (t==0) ? 0 : (t + NS_);
            __half* pp = &g_p16[((size_t)b*LT_ + slot)*LP_];
            pp[197] = __ushort_as_half(0); pp[198] = __ushort_as_half(0);
            pp[199] = __ushort_as_half(0);
        }
    }

    const uint4 z4 = make_uint4(0,0,0,0);
    #pragma unroll
    for (int i = 0; i < 2; i++){
        int idx = i*256 + tid;
        int r = idx >> 3, c8 = (idx & 7) * 8;
        int tg = tt*64 + r;
        uint4 v = z4;
        if (tg < L_) v = *(const uint4*)&qb[(size_t)tg*HD_ + c8];
        *(uint4*)(Qs + r*STR2 + c8) = v;
    }

    int wm = (wid & 3) * 16, wn = (wid >> 2) * 32;
    uint32_t aQ = smem_u32(Qs) + (uint32_t)((wm + (lane & 15))*144 + (lane >> 4)*16);
    int rowB = wn + (lane & 7) + ((lane >> 4) & 1)*8;
    uint32_t aKh = smem_u32(Kh) + (uint32_t)(rowB*144 + ((lane >> 3) & 1)*16);
    uint32_t aKl = smem_u32(Kl) + (uint32_t)(rowB*144 + ((lane >> 3) & 1)*16);

    int rr[2], cc8[2];
    #pragma unroll
    for (int i = 0; i < 2; i++){
        int idx = i*256 + tid;
        rr[i] = idx >> 3; cc8[i] = (idx & 7) * 8;
    }

    uint4 pvh[2], pvl[2];
    #pragma unroll
    for (int i = 0; i < 2; i++){
        int sg = rr[i];
        pvh[i] = z4; pvl[i] = z4;
        if (sg < L_){
            pvh[i] = *(const uint4*)&kbh[(size_t)sg*HD_ + cc8[i]];
            pvl[i] = *(const uint4*)&kbl[(size_t)sg*HD_ + cc8[i]];
        }
    }

    float acc[4][4][4];   // [ts][ni][c]
    #pragma unroll
    for (int a=0;a<4;a++)
        #pragma unroll
        for (int i=0;i<4;i++)
            #pragma unroll
            for (int j=0;j<4;j++) acc[a][i][j] = 0.f;

    for (int ts = 0; ts < 4; ts++){
        __syncthreads();
        #pragma unroll
        for (int i = 0; i < 2; i++){
            *(uint4*)(Kh + rr[i]*STR2 + cc8[i]) = pvh[i];
            *(uint4*)(Kl + rr[i]*STR2 + cc8[i]) = pvl[i];
        }
        __syncthreads();

        if (ts + 1 < 4){
            #pragma unroll
            for (int i = 0; i < 2; i++){
                int sg = (ts+1)*64 + rr[i];
                pvh[i] = z4; pvl[i] = z4;
                if (sg < L_){
                    pvh[i] = *(const uint4*)&kbh[(size_t)sg*HD_ + cc8[i]];
                    pvl[i] = *(const uint4*)&kbl[(size_t)sg*HD_ + cc8[i]];
                }
            }
        }

        #pragma unroll
        for (int ks = 0; ks < 4; ks++){
            uint32_t a[4];
            ldsm_x4(a, aQ + ks*32);
            #pragma unroll
            for (int q = 0; q < 2; q++){
                uint32_t bh[4], bl[4];
                ldsm_x4(bh, aKh + ks*32 + q*16*144);
                ldsm_x4(bl, aKl + ks*32 + q*16*144);
                mma_f16(acc[ts][2*q],   a, bh);
                mma_f16(acc[ts][2*q+1], a, bh+2);
                mma_f16(acc[ts][2*q],   a, bl);
                mma_f16(acc[ts][2*q+1], a, bl+2);
            }
        }
    }

    // ---- fused softmax over the full row (registers + tiny smem exchange) ----
    int t0 = tt*64 + wm + (lane >> 2);
    int t1 = t0 + 8;
    int sb = wn + (lane & 3)*2;   // col base (add ts*64 + ni*8)

    // scale raw scores
    #pragma unroll
    for (int ts=0; ts<4; ts++)
        #pragma unroll
        for (int ni=0; ni<4; ni++)
            #pragma unroll
            for (int c=0; c<4; c++) acc[ts][ni][c] *= DESCALE;

    // raw center row for rand
    if (t0 == 0){
        float* dst = &g_attn[(size_t)b*LT_*LP_];
        #pragma unroll
        for (int ts=0; ts<4; ts++)
            #pragma unroll
            for (int ni=0; ni<4; ni++){
                int s = ts*64 + ni*8 + sb;
                if (s   < L_) dst[s]   = acc[ts][ni][0];
                if (s+1 < L_) dst[s+1] = acc[ts][ni][1];
            }
    }

    // partial max (masked)
    float m0 = NEG_INF, m1 = NEG_INF;
    #pragma unroll
    for (int ts=0; ts<4; ts++)
        #pragma unroll
        for (int ni=0; ni<4; ni++){
            int s = ts*64 + ni*8 + sb;
            if (s < L_){ m0 = fmaxf(m0, acc[ts][ni][0]); m1 = fmaxf(m1, acc[ts][ni][2]); }
            if (s+1 < L_){ m0 = fmaxf(m0, acc[ts][ni][1]); m1 = fmaxf(m1, acc[ts][ni][3]); }
        }
    #pragma unroll
    for (int o=1;o<=2;o<<=1){
        m0 = fmaxf(m0, __shfl_xor_sync(0xffffffffu, m0, o));
        m1 = fmaxf(m1, __shfl_xor_sync(0xffffffffu, m1, o));
    }
    if ((lane & 3) == 0){
        xch[wid][lane>>2] = m0;
        xch[wid][8 + (lane>>2)] = m1;
    }
    __syncthreads();
    m0 = fmaxf(m0, xch[wid^4][lane>>2]);
    m1 = fmaxf(m1, xch[wid^4][8 + (lane>>2)]);

    // exp in place + partial sum
    float s0 = 0.f, s1 = 0.f;
    #pragma unroll
    for (int ts=0; ts<4; ts++)
        #pragma unroll
        for (int ni=0; ni<4; ni++){
            int s = ts*64 + ni*8 + sb;
            float e0 = (s   < L_) ? expf(acc[ts][ni][0] - m0) : 0.f;
            float e1 = (s+1 < L_) ? expf(acc[ts][ni][1] - m0) : 0.f;
            float e2 = (s   < L_) ? expf(acc[ts][ni][2] - m1) : 0.f;
            float e3 = (s+1 < L_) ? expf(acc[ts][ni][3] - m1) : 0.f;
            acc[ts][ni][0] = e0; acc[ts][ni][1] = e1;
            acc[ts][ni][2] = e2; acc[ts][ni][3] = e3;
            s0 += e0 + e1; s1 += e2 + e3;
        }
    #pragma unroll
    for (int o=1;o<=2;o<<=1){
        s0 += __shfl_xor_sync(0xffffffffu, s0, o);
        s1 += __shfl_xor_sync(0xffffffffu, s1, o);
    }
    __syncthreads();   // xch max reads done
    if ((lane & 3) == 0){
        xch[wid][lane>>2] = s0;
        xch[wid][8 + (lane>>2)] = s1;
    }
    __syncthreads();
    s0 += xch[wid^4][lane>>2];
    s1 += xch[wid^4][8 + (lane>>2)];
    float inv0 = 1.0f / s0, inv1 = 1.0f / s1;

    // write normalized fp16 probs
    int slot0 = (t0==0) ? 0 : (t0 + NS_);
    int slot1 = t1 + NS_;     // t1 >= 8, never 0
    __half* d0 = (t0 < L_) ? &g_p16[((size_t)b*LT_ + slot0)*LP_] : nullptr;
    __half* d1 = (t1 < L_) ? &g_p16[((size_t)b*LT_ + slot1)*LP_] : nullptr;
    #pragma unroll
    for (int ts=0; ts<4; ts++)
        #pragma unroll
        for (int ni=0; ni<4; ni++){
            int s = ts*64 + ni*8 + sb;
            if (s >= L_) continue;
            bool two = (s + 1 < L_);
            if (d0){
                if (two){
                    __half2 h = __floats2half2_rn(acc[ts][ni][0]*inv0, acc[ts][ni][1]*inv0);
                    *(uint32_t*)&d0[s] = *(uint32_t*)&h;
                } else d0[s] = __float2half_rn(acc[ts][ni][0]*inv0);
            }
            if (d1){
                if (two){
                    __half2 h = __floats2half2_rn(acc[ts][ni][2]*inv1, acc[ts][ni][3]*inv1);
                    *(uint32_t*)&d1[s] = *(uint32_t*)&h;
                } else d1[s] = __float2half_rn(acc[ts][ni][2]*inv1);
            }
        }
}

// ---------------- 5. AV -> fp16 X (pipelined; probs fp16, V via ldmatrix.trans) -------
__global__ __launch_bounds__(256, 2) void av_mma()
{
    __shared__ __align__(16) __half Ahs[64*STR2];
    __shared__ __align__(16) __half Vh[64*STR2], Vl[64*STR2];

    int b = blockIdx.x, tT = blockIdx.y;
    int tid = threadIdx.x, lane = tid & 31, wid = tid >> 5;
    const __half* attn_b = g_p16 + (size_t)b*LT_*LP_;
    const __half* vbh = g_vh + (size_t)b*L_*HD_;
    const __half* vbl = g_vl + (size_t)b*L_*HD_;

    int wm = (wid & 3) * 16, wn = (wid >> 2) * 32;
    uint32_t aA = smem_u32(Ahs) + (uint32_t)((wm + (lane & 15))*144 + (lane >> 4)*16);
    uint32_t aVh = smem_u32(Vh) + (uint32_t)((lane & 15)*144 + (wn + (lane >> 4)*8)*2);
    uint32_t aVl = smem_u32(Vl) + (uint32_t)((lane & 15)*144 + (wn + (lane >> 4)*8)*2);

    float acc[4][4];
    #pragma unroll
    for (int i=0;i<4;i++)
        #pragma unroll
        for (int j=0;j<4;j++) acc[i][j] = 0.f;

    const uint4 z4 = make_uint4(0,0,0,0);
    int rr[2], cc8[2];
    #pragma unroll
    for (int i = 0; i < 2; i++){
        int idx = i*256 + tid;
        rr[i] = idx >> 3; cc8[i] = (idx & 7) * 8;
    }

    uint4 pa[2], pvh[2], pvl[2];
    #pragma unroll
    for (int i = 0; i < 2; i++){
        int t = tT*64 + rr[i];
        pa[i] = z4;
        if (t < LT_ && cc8[i] + 8 <= LP_)
            pa[i] = *(const uint4*)&attn_b[(size_t)t*LP_ + cc8[i]];
        int sv = rr[i];
        pvh[i] = z4; pvl[i] = z4;
        if (sv < L_){
            pvh[i] = *(const uint4*)&vbh[(size_t)sv*HD_ + cc8[i]];
            pvl[i] = *(const uint4*)&vbl[(size_t)sv*HD_ + cc8[i]];
        }
    }

    for (int s0 = 0; s0 < L_; s0 += 64){
        __syncthreads();
        #pragma unroll
        for (int i = 0; i < 2; i++){
            *(uint4*)(Ahs + rr[i]*STR2 + cc8[i]) = pa[i];
            *(uint4*)(Vh  + rr[i]*STR2 + cc8[i]) = pvh[i];
            *(uint4*)(Vl  + rr[i]*STR2 + cc8[i]) = pvl[i];
        }
        __syncthreads();

        int s1 = s0 + 64;
        if (s1 < L_){
            #pragma unroll
            for (int i = 0; i < 2; i++){
                int t = tT*64 + rr[i];
                int s = s1 + cc8[i];
                pa[i] = z4;
                if (t < LT_ && s + 8 <= LP_)
                    pa[i] = *(const uint4*)&attn_b[(size_t)t*LP_ + s];
                int sv = s1 + rr[i];
                pvh[i] = z4; pvl[i] = z4;
                if (sv < L_){
                    pvh[i] = *(const uint4*)&vbh[(size_t)sv*HD_ + cc8[i]];
                    pvl[i] = *(const uint4*)&vbl[(size_t)sv*HD_ + cc8[i]];
                }
            }
        }

        #pragma unroll
        for (int ks = 0; ks < 4; ks++){
            uint32_t a[4];
            ldsm_x4(a, aA + ks*32);
            #pragma unroll
            for (int q = 0; q < 2; q++){
                uint32_t bh[4], bl[4];
                ldsm_x4t(bh, aVh + ks*16*144 + q*32);
                ldsm_x4t(bl, aVl + ks*16*144 + q*32);
                mma_f16(acc[2*q],   a, bh);
                mma_f16(acc[2*q+1], a, bh+2);
                mma_f16(acc[2*q],   a, bl);
                mma_f16(acc[2*q+1], a, bl+2);
            }
        }
    }

    int n = b / H_, h = b % H_;
    int t0 = tT*64 + wm + (lane >> 2);
    int t1 = t0 + 8;
    #pragma unroll
    for (int ni = 0; ni < 4; ni++){
        int d = wn + ni*8 + (lane & 3)*2;
        #pragma unroll
        for (int half = 0; half < 2; half++){
            int t = half ? t1 : t0;
            if (t >= LT_) continue;
            __half2 hh = __floats2half2_rn(acc[ni][half*2]*DESCALE,
                                           acc[ni][half*2+1]*DESCALE);
            *(uint32_t*)&g_xh[((size_t)t*NB_ + n)*E_ + h*HD_ + d] = *(uint32_t*)&hh;
        }
    }
}

// ---------------- threefry2x32 (bit-exact JAX, partitionable) ----------------
__device__ __forceinline__ uint32_t rotl32(uint32_t x, int r){ return (x<<r)|(x>>(32-r)); }

__device__ __forceinline__ void tf2x32(uint32_t k0, uint32_t k1, uint32_t x0, uint32_t x1,
                                       uint32_t &o0, uint32_t &o1)
{
    uint32_t ks2 = k0 ^ k1 ^ 0x1BD11BDAu;
#define TFR(r) { x0 += x1; x1 = rotl32(x1, (r)); x1 ^= x0; }
    x0 += k0; x1 += k1;
    TFR(13) TFR(15) TFR(26) TFR(6)
    x0 += k1;  x1 += ks2 + 1u;
    TFR(17) TFR(29) TFR(16) TFR(24)
    x0 += ks2; x1 += k0 + 2u;
    TFR(13) TFR(15) TFR(26) TFR(6)
    x0 += k0;  x1 += k1 + 3u;
    TFR(17) TFR(29) TFR(16) TFR(24)
    x0 += k1;  x1 += ks2 + 4u;
    TFR(13) TFR(15) TFR(26) TFR(6)
    x0 += ks2; x1 += k0 + 5u;
#undef TFR
    o0 = x0; o1 = x1;
}

__device__ __forceinline__ uint32_t rbits32(uint32_t ka, uint32_t kb, uint32_t i){
    uint32_t o0, o1;
    tf2x32(ka, kb, 0u, i, o0, o1);
    return o0 ^ o1;
}

__device__ __forceinline__ float u01(uint32_t bits){
    return __uint_as_float((bits >> 9) | 0x3f800000u) - 1.0f;
}

__device__ __forceinline__ float blockSum256(float v, float* red){
    #pragma unroll
    for (int o=16;o>0;o>>=1) v += __shfl_xor_sync(0xffffffffu, v, o);
    __syncthreads();
    if ((threadIdx.x & 31) == 0) red[threadIdx.x >> 5] = v;
    __syncthreads();
    float s = red[0];
    #pragma unroll
    for (int i=1;i<8;i++) s += red[i];
    return s;
}

__device__ __forceinline__ float warpSum(float v){
    #pragma unroll
    for (int o=16;o>0;o>>=1) v += __shfl_xor_sync(0xffffffffu, v, o);
    return v;
}

// ---------------- 3. random rows: warp-per-sample, fused softmax -> fp16 probs ------
__global__ __launch_bounds__(256) void rand_kernel()
{
    int b   = blockIdx.x;
    int tid = threadIdx.x, lid = tid & 31, wid = tid >> 5;
    __shared__ float u[L_];
    __shared__ float red[8];
    __shared__ float norm_sh;

    uint32_t k1a, k1b, k2a, k2b;
    tf2x32(0u, 1234u, 0u, 0u, k1a, k1b);
    tf2x32(0u, 1234u, 0u, 1u, k2a, k2b);

    float c = 0.f;
    if (tid < L_) c = g_attn[(size_t)b*LT_*LP_ + tid];   // raw center row
    float ss = blockSum256(c*c, red);
    if (tid == 0) norm_sh = sqrtf(ss);
    __syncthreads();
    float norm = norm_sh;
    float nden = fmaxf(norm, 1e-12f);
    if (tid < L_) u[tid] = c / nden;
    __syncthreads();

    for (int n = wid; n < NS_; n += 8){
        float fc = u01(rbits32(k2a, k2b, (uint32_t)n));
        float cosn = fc * 0.2f + 0.7f;
        float sinn = sqrtf(1.0f - cosn*cosn);

        float r[7], uu[7];
        float dot = 0.f;
        uint32_t base = ((uint32_t)n*1536u + (uint32_t)b)*197u;
        #pragma unroll
        for (int i = 0; i < 7; i++){
            int idx = i*32 + lid;
            if (idx < L_){
                r[i]  = u01(rbits32(k1a, k1b, base + (uint32_t)idx)) * 2.0f - 1.0f;
                uu[i] = u[idx];
            } else { r[i] = 0.f; uu[i] = 0.f; }
            dot += r[i]*uu[i];
        }
        dot = warpSum(dot);
        float tsum = 0.f;
        #pragma unroll
        for (int i = 0; i < 7; i++){
            r[i] = r[i] - dot*uu[i];
            tsum += r[i]*r[i];
        }
        tsum = warpSum(tsum);
        float inv = 1.0f / fmaxf(sqrtf(tsum), 1e-12f);

        float w[7];
        float m = NEG_INF;
        #pragma unroll
        for (int i = 0; i < 7; i++){
            int idx = i*32 + lid;
            w[i] = (idx < L_) ? (cosn*uu[i] + sinn*(r[i]*inv)) * norm : NEG_INF;
            m = fmaxf(m, w[i]);
        }
        #pragma unroll
        for (int o=16;o>0;o>>=1) m = fmaxf(m, __shfl_xor_sync(0xffffffffu, m, o));
        float s = 0.f;
        #pragma unroll
        for (int i = 0; i < 7; i++){
            w[i] = expf(w[i] - m);
            s += w[i];
        }
        s = warpSum(s);
        float sinv = 1.0f / s;

        __half* dst = &g_p16[((size_t)b*LT_ + 1 + n)*LP_];
        #pragma unroll
        for (int i = 0; i < 7; i++){
            int idx = i*32 + lid;
            if (idx < L_) dst[idx] = __float2half_rn(w[i] * sinv);
            else if (idx < LP_) dst[idx] = __ushort_as_half((unsigned short)0);
        }
    }
}

// ---------------- 7. attn_weights = mean over heads (fp16 probs) ----------------
__global__ __launch_bounds__(256) void mean_kernel(float* __restrict__ aw)
{
    int idx = blockIdx.x * 256 + threadIdx.x;
    if (idx >= AW_ELEMS) return;
    int s = idx % L_;
    int t = (idx / L_) % LT_;
    int n = idx / (L_ * LT_);
    float sum = 0.f;
    #pragma unroll
    for (int h=0; h<H_; h++)
        sum += __half2float(g_p16[(((size_t)(n*H_ + h))*LT_ + t)*LP_ + s]);
    aw[idx] = sum * (1.0f/12.0f);
}

// ---------------- launch ----------------
extern "C" void kernel_launch(void* const* d_in, const int* in_sizes, int n_in,
                              void* d_out, int out_size)
{
    const float* q   = (const float*)d_in[0];
    const float* k   = (const float*)d_in[1];
    const float* v   = (const float*)d_in[2];
    const float* ipw = (const float*)d_in[3];
    const float* ipb = (const float*)d_in[4];
    const float* opw = (const float*)d_in[5];
    const float* opb = (const float*)d_in[6];
    float* out = (float*)d_out;

    __half *ah, *wh, *wl;
    cudaGetSymbolAddress((void**)&ah, g_ah);
    cudaGetSymbolAddress((void**)&wh, g_wh);
    cudaGetSymbolAddress((void**)&wl, g_wl);

    const int n4in = IN_ELEMS/4;
    round_all<<<dim3((n4in+255)/256, 3), 256>>>(q, k, v, ah, n4in);
    splitw_all<<<(4*W_ELEMS/4+255)/256, 256>>>(ipw, opw, wh, wl);

    proj_tc<<<dim3(6,197,3), 256>>>(ipb);
    qk_mma<<<dim3(1536,4), 256>>>();
    rand_kernel<<<1536, 256>>>();
    av_mma<<<dim3(1536,5), 256>>>();
    out_tc<<<dim3(6,257), 256>>>(opb, out);
    mean_kernel<<<(AW_ELEMS + 255)/256, 256>>>(out + OUT_ELEMS);
}

// round 17
// speedup vs baseline: 1.1171x; 1.1055x over previous
#include <cuda_runtime.h>
#include <cuda_fp16.h>
#include <cstdint>

#define L_   197
#define LP_  200
#define NB_  128
#define E_   768
#define H_   12
#define HD_  64
#define B_   1536
#define NS_  60
#define LT_  257
#define OUT_ELEMS 25264128
#define AW_ELEMS  6480512

#define STRH 40        // proj/out smem row stride in halves (80 B)
#define STR2 72        // qk/av smem row stride in halves (144 B)

#define IN_ELEMS 19365888        // 25216*768
#define W_ELEMS  589824          // 768*768
#define DESCALE 0.00390625f      // 2^-8
#define NEG_INF -3.402823466e38f

// ---------------- scratch ----------------
__device__ float  g_attn[78950400];      // (B, LT, LP_) raw center rows only
__device__ __half g_p16[78950400];       // (B, LT, LP_) post-softmax probs (fp16)
__device__ __half g_ah[3*IN_ELEMS];      // inputs rounded to fp16 (proj A)
__device__ __half g_wh[4*W_ELEMS];       // weights*256 hi
__device__ __half g_wl[4*W_ELEMS];       // weights*256 lo
__device__ __half g_qh[IN_ELEMS];        // q fp16 (scaled by 1/8), (b,l,d)
__device__ __half g_kh[IN_ELEMS];        // k*256 hi, (b,l,d)
__device__ __half g_kl[IN_ELEMS];        // k*256 lo
__device__ __half g_vh[IN_ELEMS];        // v*256 hi (single term)
__device__ __half g_xh[OUT_ELEMS];       // AV output, fp16

// ================= helpers =================
__device__ __forceinline__ uint32_t smem_u32(const void* p){
    return (uint32_t)__cvta_generic_to_shared(p);
}
__device__ __forceinline__ void ldsm_x4(uint32_t* r, uint32_t addr){
    asm volatile("ldmatrix.sync.aligned.m8n8.x4.shared.b16 {%0,%1,%2,%3}, [%4];"
        : "=r"(r[0]),"=r"(r[1]),"=r"(r[2]),"=r"(r[3]) : "r"(addr));
}
__device__ __forceinline__ void ldsm_x4t(uint32_t* r, uint32_t addr){
    asm volatile("ldmatrix.sync.aligned.m8n8.x4.trans.shared.b16 {%0,%1,%2,%3}, [%4];"
        : "=r"(r[0]),"=r"(r[1]),"=r"(r[2]),"=r"(r[3]) : "r"(addr));
}
__device__ __forceinline__ void mma_f16(float* d, const uint32_t* a, const uint32_t* b){
    asm volatile("mma.sync.aligned.m16n8k16.row.col.f32.f16.f16.f32 "
        "{%0,%1,%2,%3}, {%4,%5,%6,%7}, {%8,%9}, {%0,%1,%2,%3};"
        : "+f"(d[0]),"+f"(d[1]),"+f"(d[2]),"+f"(d[3])
        : "r"(a[0]),"r"(a[1]),"r"(a[2]),"r"(a[3]), "r"(b[0]),"r"(b[1]));
}

// ---------------- 0a. round fp32 -> fp16 (3 inputs in one launch) ----------------
__global__ __launch_bounds__(256) void round_all(
    const float* __restrict__ q, const float* __restrict__ k,
    const float* __restrict__ v, __half* __restrict__ dst, int n4)
{
    int i = blockIdx.x * 256 + threadIdx.x;
    if (i >= n4) return;
    const float* src = (blockIdx.y == 0) ? q : ((blockIdx.y == 1) ? k : v);
    float4 f = ((const float4*)src)[i];
    __half2 h01 = __floats2half2_rn(f.x, f.y);
    __half2 h23 = __floats2half2_rn(f.z, f.w);
    *(uint2*)(dst + (size_t)blockIdx.y*IN_ELEMS + 4*(size_t)i) =
        make_uint2(*(uint32_t*)&h01, *(uint32_t*)&h23);
}

// ---------------- 0b. split (256*w) -> fp16 hi/lo, both weight mats ----------------
__global__ __launch_bounds__(256) void splitw_all(
    const float* __restrict__ ipw, const float* __restrict__ opw,
    __half* __restrict__ dh, __half* __restrict__ dl)
{
    int i = blockIdx.x * 256 + threadIdx.x;
    const int n4ip = 3*W_ELEMS/4;
    float4 f;
    if (i < n4ip) f = ((const float4*)ipw)[i];
    else          f = ((const float4*)opw)[i - n4ip];
    float sx = f.x*256.f, sy = f.y*256.f, sz = f.z*256.f, sw = f.w*256.f;
    __half2 h01 = __floats2half2_rn(sx, sy);
    __half2 h23 = __floats2half2_rn(sz, sw);
    __half2 l01 = __floats2half2_rn(sx - __half2float(h01.x), sy - __half2float(h01.y));
    __half2 l23 = __floats2half2_rn(sz - __half2float(h23.x), sw - __half2float(h23.y));
    *(uint2*)(dh + 4*(size_t)i) = make_uint2(*(uint32_t*)&h01, *(uint32_t*)&h23);
    *(uint2*)(dl + 4*(size_t)i) = make_uint2(*(uint32_t*)&l01, *(uint32_t*)&l23);
}

// ---- pipelined GEMM body: C(128x128) = A(128x768) * B(128x768)^T ----
// SPLIT=1: B = Bh + Bl (2-term). SPLIT=0: B = Bh only (Bl unused).
template<int SPLIT>
__device__ __forceinline__ void gemm_body16(
    const __half* __restrict__ Ag, const __half* __restrict__ Bh,
    const __half* __restrict__ Bl,
    __half* sA, __half* sBh, __half* sBl,
    float acc[2][8][4], int tid)
{
    int lane = tid & 31, wid = tid >> 5;
    int wm = (wid & 3) * 32, wn = (wid >> 2) * 64;

    uint32_t aA = smem_u32(sA) + (uint32_t)((wm + (lane & 15))*80 + (lane >> 4)*16);
    int rowB = wn + (lane & 7) + ((lane >> 4) & 1)*8;
    uint32_t oBh = smem_u32(sBh) + (uint32_t)(rowB*80 + ((lane >> 3) & 1)*16);
    uint32_t oBl = smem_u32(sBl) + (uint32_t)(rowB*80 + ((lane >> 3) & 1)*16);

    int rr[2], ss[2];
    #pragma unroll
    for (int j = 0; j < 2; j++){
        int idx = j*256 + tid;
        rr[j] = idx >> 2;
        ss[j] = (idx & 3) * 8;
    }
    size_t go0 = (size_t)rr[0]*E_ + ss[0];
    size_t go1 = (size_t)rr[1]*E_ + ss[1];

    uint4 va[2], vh[2], vl[2];
    va[0] = *(const uint4*)(Ag + go0); va[1] = *(const uint4*)(Ag + go1);
    vh[0] = *(const uint4*)(Bh + go0); vh[1] = *(const uint4*)(Bh + go1);
    if (SPLIT){ vl[0] = *(const uint4*)(Bl + go0); vl[1] = *(const uint4*)(Bl + go1); }

    for (int ch = 0; ch < 24; ch++){
        __syncthreads();
        #pragma unroll
        for (int j = 0; j < 2; j++){
            int so = rr[j]*STRH + ss[j];
            *(uint4*)(sA  + so) = va[j];
            *(uint4*)(sBh + so) = vh[j];
            if (SPLIT) *(uint4*)(sBl + so) = vl[j];
        }
        __syncthreads();

        if (ch + 1 < 24){
            int kB = (ch+1) * 32;
            va[0] = *(const uint4*)(Ag + go0 + kB); va[1] = *(const uint4*)(Ag + go1 + kB);
            vh[0] = *(const uint4*)(Bh + go0 + kB); vh[1] = *(const uint4*)(Bh + go1 + kB);
            if (SPLIT){
                vl[0] = *(const uint4*)(Bl + go0 + kB); vl[1] = *(const uint4*)(Bl + go1 + kB);
            }
        }

        #pragma unroll
        for (int ks = 0; ks < 2; ks++){
            uint32_t a0[4], a1[4];
            ldsm_x4(a0, aA + ks*32);
            ldsm_x4(a1, aA + ks*32 + 16*80);
            #pragma unroll
            for (int q = 0; q < 4; q++){
                uint32_t bh[4];
                ldsm_x4(bh, oBh + ks*32 + q*16*80);
                mma_f16(acc[0][2*q],   a0, bh);
                mma_f16(acc[0][2*q+1], a0, bh+2);
                mma_f16(acc[1][2*q],   a1, bh);
                mma_f16(acc[1][2*q+1], a1, bh+2);
                if (SPLIT){
                    uint32_t bl[4];
                    ldsm_x4(bl, oBl + ks*32 + q*16*80);
                    mma_f16(acc[0][2*q],   a0, bl);
                    mma_f16(acc[0][2*q+1], a0, bl+2);
                    mma_f16(acc[1][2*q],   a1, bl);
                    mma_f16(acc[1][2*q+1], a1, bl+2);
                }
            }
        }
    }
}

// ---------------- 1. QKV projection; epilogue emits MMA-ready fp16 ----------------
__global__ __launch_bounds__(256, 2) void proj_tc(const float* __restrict__ bias)
{
    __shared__ __align__(16) __half sA[128*STRH], sBh[128*STRH], sBl[128*STRH];

    int tid = threadIdx.x, lane = tid & 31, wid = tid >> 5;
    int p = blockIdx.z;
    const __half* Ah = g_ah + (size_t)p*IN_ELEMS;
    const __half* Bh = g_wh + (size_t)p*W_ELEMS;
    const __half* Bl = g_wl + (size_t)p*W_ELEMS;
    const float* bp = bias + (size_t)p*E_;

    int l = blockIdx.y;
    int nBase = blockIdx.x * 128;
    size_t mBase = (size_t)l * 128;

    float acc[2][8][4];
    #pragma unroll
    for (int i=0;i<2;i++)
        #pragma unroll
        for (int j=0;j<8;j++)
            #pragma unroll
            for (int c=0;c<4;c++) acc[i][j][c] = 0.f;

    gemm_body16<1>(Ah + mBase*E_, Bh + (size_t)nBase*E_, Bl + (size_t)nBase*E_,
                   sA, sBh, sBl, acc, tid);

    int wm = (wid & 3) * 32, wn = (wid >> 2) * 64;
    #pragma unroll
    for (int mi = 0; mi < 2; mi++){
        int r = wm + mi*16 + (lane >> 2);
        #pragma unroll
        for (int ni = 0; ni < 8; ni++){
            int col = wn + ni*8 + (lane & 3)*2;
            int gc  = nBase + col;
            int h = gc >> 6, d = gc & 63;
            float b0 = bp[gc], b1 = bp[gc+1];
            float v00 = acc[mi][ni][0]*DESCALE + b0;
            float v01 = acc[mi][ni][1]*DESCALE + b1;
            float v10 = acc[mi][ni][2]*DESCALE + b0;
            float v11 = acc[mi][ni][3]*DESCALE + b1;
            size_t o0 = (((size_t)(r*H_ + h))*L_ + l)*HD_ + d;
            size_t o1 = (((size_t)((r+8)*H_ + h))*L_ + l)*HD_ + d;
            if (p == 0){
                __half2 q0 = __floats2half2_rn(v00*0.125f, v01*0.125f);
                __half2 q1 = __floats2half2_rn(v10*0.125f, v11*0.125f);
                *(uint32_t*)&g_qh[o0] = *(uint32_t*)&q0;
                *(uint32_t*)&g_qh[o1] = *(uint32_t*)&q1;
            } else if (p == 1){
                float s00 = v00*256.f, s01 = v01*256.f, s10 = v10*256.f, s11 = v11*256.f;
                __half2 h0 = __floats2half2_rn(s00, s01);
                __half2 h1 = __floats2half2_rn(s10, s11);
                __half2 l0 = __floats2half2_rn(s00 - __half2float(h0.x), s01 - __half2float(h0.y));
                __half2 l1 = __floats2half2_rn(s10 - __half2float(h1.x), s11 - __half2float(h1.y));
                *(uint32_t*)&g_kh[o0] = *(uint32_t*)&h0;
                *(uint32_t*)&g_kh[o1] = *(uint32_t*)&h1;
                *(uint32_t*)&g_kl[o0] = *(uint32_t*)&l0;
                *(uint32_t*)&g_kl[o1] = *(uint32_t*)&l1;
            } else {
                // v: single-term fp16 (x256 for consistency with DESCALE in av)
                __half2 h0 = __floats2half2_rn(v00*256.f, v01*256.f);
                __half2 h1 = __floats2half2_rn(v10*256.f, v11*256.f);
                *(uint32_t*)&g_vh[o0] = *(uint32_t*)&h0;
                *(uint32_t*)&g_vh[o1] = *(uint32_t*)&h1;
            }
        }
    }
}

// ---------------- 6. out projection (single-term W) ----------------
__global__ __launch_bounds__(256, 2) void out_tc(
    const float* __restrict__ bias, float* __restrict__ outp)
{
    __shared__ __align__(16) __half sA[128*STRH], sBh[128*STRH];

    int tid = threadIdx.x, lane = tid & 31, wid = tid >> 5;
    size_t mBase = (size_t)blockIdx.y * 128;
    int nBase = blockIdx.x * 128;

    float acc[2][8][4];
    #pragma unroll
    for (int i=0;i<2;i++)
        #pragma unroll
        for (int j=0;j<8;j++)
            #pragma unroll
            for (int c=0;c<4;c++) acc[i][j][c] = 0.f;

    gemm_body16<0>(g_xh + mBase*E_,
                   g_wh + (size_t)3*W_ELEMS + (size_t)nBase*E_,
                   nullptr,
                   sA, sBh, sBh, acc, tid);

    int wm = (wid & 3) * 32, wn = (wid >> 2) * 64;
    #pragma unroll
    for (int mi = 0; mi < 2; mi++){
        int r = wm + mi*16 + (lane >> 2);
        #pragma unroll
        for (int ni = 0; ni < 8; ni++){
            int col = wn + ni*8 + (lane & 3)*2;
            int gc  = nBase + col;
            float b0 = bias[gc], b1 = bias[gc+1];
            float2 v0 = make_float2(acc[mi][ni][0]*DESCALE + b0,
                                    acc[mi][ni][1]*DESCALE + b1);
            float2 v1 = make_float2(acc[mi][ni][2]*DESCALE + b0,
                                    acc[mi][ni][3]*DESCALE + b1);
            *(float2*)&outp[(mBase + r)*E_ + gc] = v0;
            *(float2*)&outp[(mBase + r + 8)*E_ + gc] = v1;
        }
    }
}

// ---------------- 2. QK^T with register-resident FUSED SOFTMAX -> fp16 probs --------
__global__ __launch_bounds__(256) void qk_mma()
{
    __shared__ __align__(16) __half Qs[64*STR2];
    __shared__ __align__(16) __half Kh[64*STR2], Kl[64*STR2];
    __shared__ float xch[8][16];

    int b = blockIdx.x, tt = blockIdx.y;
    int tid = threadIdx.x, lane = tid & 31, wid = tid >> 5;
    const __half* qb  = g_qh + (size_t)b*L_*HD_;
    const __half* kbh = g_kh + (size_t)b*L_*HD_;
    const __half* kbl = g_kl + (size_t)b*L_*HD_;

    if (tid < 64){
        int t = tt*64 + tid;
        if (t < L_){
            int slot = (t==0) ? 0 : (t + NS_);
            __half* pp = &g_p16[((size_t)b*LT_ + slot)*LP_];
            pp[197] = __ushort_as_half(0); pp[198] = __ushort_as_half(0);
            pp[199] = __ushort_as_half(0);
        }
    }

    const uint4 z4 = make_uint4(0,0,0,0);
    #pragma unroll
    for (int i = 0; i < 2; i++){
        int idx = i*256 + tid;
        int r = idx >> 3, c8 = (idx & 7) * 8;
        int tg = tt*64 + r;
        uint4 v = z4;
        if (tg < L_) v = *(const uint4*)&qb[(size_t)tg*HD_ + c8];
        *(uint4*)(Qs + r*STR2 + c8) = v;
    }

    int wm = (wid & 3) * 16, wn = (wid >> 2) * 32;
    uint32_t aQ = smem_u32(Qs) + (uint32_t)((wm + (lane & 15))*144 + (lane >> 4)*16);
    int rowB = wn + (lane & 7) + ((lane >> 4) & 1)*8;
    uint32_t aKh = smem_u32(Kh) + (uint32_t)(rowB*144 + ((lane >> 3) & 1)*16);
    uint32_t aKl = smem_u32(Kl) + (uint32_t)(rowB*144 + ((lane >> 3) & 1)*16);

    int rr[2], cc8[2];
    #pragma unroll
    for (int i = 0; i < 2; i++){
        int idx = i*256 + tid;
        rr[i] = idx >> 3; cc8[i] = (idx & 7) * 8;
    }

    uint4 pvh[2], pvl[2];
    #pragma unroll
    for (int i = 0; i < 2; i++){
        int sg = rr[i];
        pvh[i] = z4; pvl[i] = z4;
        if (sg < L_){
            pvh[i] = *(const uint4*)&kbh[(size_t)sg*HD_ + cc8[i]];
            pvl[i] = *(const uint4*)&kbl[(size_t)sg*HD_ + cc8[i]];
        }
    }

    float acc[4][4][4];   // [ts][ni][c]
    #pragma unroll
    for (int a=0;a<4;a++)
        #pragma unroll
        for (int i=0;i<4;i++)
            #pragma unroll
            for (int j=0;j<4;j++) acc[a][i][j] = 0.f;

    for (int ts = 0; ts < 4; ts++){
        __syncthreads();
        #pragma unroll
        for (int i = 0; i < 2; i++){
            *(uint4*)(Kh + rr[i]*STR2 + cc8[i]) = pvh[i];
            *(uint4*)(Kl + rr[i]*STR2 + cc8[i]) = pvl[i];
        }
        __syncthreads();

        if (ts + 1 < 4){
            #pragma unroll
            for (int i = 0; i < 2; i++){
                int sg = (ts+1)*64 + rr[i];
                pvh[i] = z4; pvl[i] = z4;
                if (sg < L_){
                    pvh[i] = *(const uint4*)&kbh[(size_t)sg*HD_ + cc8[i]];
                    pvl[i] = *(const uint4*)&kbl[(size_t)sg*HD_ + cc8[i]];
                }
            }
        }

        #pragma unroll
        for (int ks = 0; ks < 4; ks++){
            uint32_t a[4];
            ldsm_x4(a, aQ + ks*32);
            #pragma unroll
            for (int q = 0; q < 2; q++){
                uint32_t bh[4], bl[4];
                ldsm_x4(bh, aKh + ks*32 + q*16*144);
                ldsm_x4(bl, aKl + ks*32 + q*16*144);
                mma_f16(acc[ts][2*q],   a, bh);
                mma_f16(acc[ts][2*q+1], a, bh+2);
                mma_f16(acc[ts][2*q],   a, bl);
                mma_f16(acc[ts][2*q+1], a, bl+2);
            }
        }
    }

    // ---- fused softmax ----
    int t0 = tt*64 + wm + (lane >> 2);
    int t1 = t0 + 8;
    int sb = wn + (lane & 3)*2;

    #pragma unroll
    for (int ts=0; ts<4; ts++)
        #pragma unroll
        for (int ni=0; ni<4; ni++)
            #pragma unroll
            for (int c=0; c<4; c++) acc[ts][ni][c] *= DESCALE;

    if (t0 == 0){
        float* dst = &g_attn[(size_t)b*LT_*LP_];
        #pragma unroll
        for (int ts=0; ts<4; ts++)
            #pragma unroll
            for (int ni=0; ni<4; ni++){
                int s = ts*64 + ni*8 + sb;
                if (s   < L_) dst[s]   = acc[ts][ni][0];
                if (s+1 < L_) dst[s+1] = acc[ts][ni][1];
            }
    }

    float m0 = NEG_INF, m1 = NEG_INF;
    #pragma unroll
    for (int ts=0; ts<4; ts++)
        #pragma unroll
        for (int ni=0; ni<4; ni++){
            int s = ts*64 + ni*8 + sb;
            if (s < L_){ m0 = fmaxf(m0, acc[ts][ni][0]); m1 = fmaxf(m1, acc[ts][ni][2]); }
            if (s+1 < L_){ m0 = fmaxf(m0, acc[ts][ni][1]); m1 = fmaxf(m1, acc[ts][ni][3]); }
        }
    #pragma unroll
    for (int o=1;o<=2;o<<=1){
        m0 = fmaxf(m0, __shfl_xor_sync(0xffffffffu, m0, o));
        m1 = fmaxf(m1, __shfl_xor_sync(0xffffffffu, m1, o));
    }
    if ((lane & 3) == 0){
        xch[wid][lane>>2] = m0;
        xch[wid][8 + (lane>>2)] = m1;
    }
    __syncthreads();
    m0 = fmaxf(m0, xch[wid^4][lane>>2]);
    m1 = fmaxf(m1, xch[wid^4][8 + (lane>>2)]);

    float s0 = 0.f, s1 = 0.f;
    #pragma unroll
    for (int ts=0; ts<4; ts++)
        #pragma unroll
        for (int ni=0; ni<4; ni++){
            int s = ts*64 + ni*8 + sb;
            float e0 = (s   < L_) ? expf(acc[ts][ni][0] - m0) : 0.f;
            float e1 = (s+1 < L_) ? expf(acc[ts][ni][1] - m0) : 0.f;
            float e2 = (s   < L_) ? expf(acc[ts][ni][2] - m1) : 0.f;
            float e3 = (s+1 < L_) ? expf(acc[ts][ni][3] - m1) : 0.f;
            acc[ts][ni][0] = e0; acc[ts][ni][1] = e1;
            acc[ts][ni][2] = e2; acc[ts][ni][3] = e3;
            s0 += e0 + e1; s1 += e2 + e3;
        }
    #pragma unroll
    for (int o=1;o<=2;o<<=1){
        s0 += __shfl_xor_sync(0xffffffffu, s0, o);
        s1 += __shfl_xor_sync(0xffffffffu, s1, o);
    }
    __syncthreads();
    if ((lane & 3) == 0){
        xch[wid][lane>>2] = s0;
        xch[wid][8 + (lane>>2)] = s1;
    }
    __syncthreads();
    s0 += xch[wid^4][lane>>2];
    s1 += xch[wid^4][8 + (lane>>2)];
    float inv0 = 1.0f / s0, inv1 = 1.0f / s1;

    int slot0 = (t0==0) ? 0 : (t0 + NS_);
    int slot1 = t1 + NS_;
    __half* d0 = (t0 < L_) ? &g_p16[((size_t)b*LT_ + slot0)*LP_] : nullptr;
    __half* d1 = (t1 < L_) ? &g_p16[((size_t)b*LT_ + slot1)*LP_] : nullptr;
    #pragma unroll
    for (int ts=0; ts<4; ts++)
        #pragma unroll
        for (int ni=0; ni<4; ni++){
            int s = ts*64 + ni*8 + sb;
            if (s >= L_) continue;
            bool two = (s + 1 < L_);
            if (d0){
                if (two){
                    __half2 h = __floats2half2_rn(acc[ts][ni][0]*inv0, acc[ts][ni][1]*inv0);
                    *(uint32_t*)&d0[s] = *(uint32_t*)&h;
                } else d0[s] = __float2half_rn(acc[ts][ni][0]*inv0);
            }
            if (d1){
                if (two){
                    __half2 h = __floats2half2_rn(acc[ts][ni][2]*inv1, acc[ts][ni][3]*inv1);
                    *(uint32_t*)&d1[s] = *(uint32_t*)&h;
                } else d1[s] = __float2half_rn(acc[ts][ni][2]*inv1);
            }
        }
}

// ---------------- 5. AV -> fp16 X (single-term V, ldmatrix.trans) ----------------
__global__ __launch_bounds__(256, 2) void av_mma()
{
    __shared__ __align__(16) __half Ahs[64*STR2];
    __shared__ __align__(16) __half Vh[64*STR2];

    int b = blockIdx.x, tT = blockIdx.y;
    int tid = threadIdx.x, lane = tid & 31, wid = tid >> 5;
    const __half* attn_b = g_p16 + (size_t)b*LT_*LP_;
    const __half* vbh = g_vh + (size_t)b*L_*HD_;

    int wm = (wid & 3) * 16, wn = (wid >> 2) * 32;
    uint32_t aA = smem_u32(Ahs) + (uint32_t)((wm + (lane & 15))*144 + (lane >> 4)*16);
    uint32_t aVh = smem_u32(Vh) + (uint32_t)((lane & 15)*144 + (wn + (lane >> 4)*8)*2);

    float acc[4][4];
    #pragma unroll
    for (int i=0;i<4;i++)
        #pragma unroll
        for (int j=0;j<4;j++) acc[i][j] = 0.f;

    const uint4 z4 = make_uint4(0,0,0,0);
    int rr[2], cc8[2];
    #pragma unroll
    for (int i = 0; i < 2; i++){
        int idx = i*256 + tid;
        rr[i] = idx >> 3; cc8[i] = (idx & 7) * 8;
    }

    uint4 pa[2], pvh[2];
    #pragma unroll
    for (int i = 0; i < 2; i++){
        int t = tT*64 + rr[i];
        pa[i] = z4;
        if (t < LT_ && cc8[i] + 8 <= LP_)
            pa[i] = *(const uint4*)&attn_b[(size_t)t*LP_ + cc8[i]];
        int sv = rr[i];
        pvh[i] = z4;
        if (sv < L_)
            pvh[i] = *(const uint4*)&vbh[(size_t)sv*HD_ + cc8[i]];
    }

    for (int s0 = 0; s0 < L_; s0 += 64){
        __syncthreads();
        #pragma unroll
        for (int i = 0; i < 2; i++){
            *(uint4*)(Ahs + rr[i]*STR2 + cc8[i]) = pa[i];
            *(uint4*)(Vh  + rr[i]*STR2 + cc8[i]) = pvh[i];
        }
        __syncthreads();

        int s1 = s0 + 64;
        if (s1 < L_){
            #pragma unroll
            for (int i = 0; i < 2; i++){
                int t = tT*64 + rr[i];
                int s = s1 + cc8[i];
                pa[i] = z4;
                if (t < LT_ && s + 8 <= LP_)
                    pa[i] = *(const uint4*)&attn_b[(size_t)t*LP_ + s];
                int sv = s1 + rr[i];
                pvh[i] = z4;
                if (sv < L_)
                    pvh[i] = *(const uint4*)&vbh[(size_t)sv*HD_ + cc8[i]];
            }
        }

        #pragma unroll
        for (int ks = 0; ks < 4; ks++){
            uint32_t a[4];
            ldsm_x4(a, aA + ks*32);
            #pragma unroll
            for (int q = 0; q < 2; q++){
                uint32_t bh[4];
                ldsm_x4t(bh, aVh + ks*16*144 + q*32);
                mma_f16(acc[2*q],   a, bh);
                mma_f16(acc[2*q+1], a, bh+2);
            }
        }
    }

    int n = b / H_, h = b % H_;
    int t0 = tT*64 + wm + (lane >> 2);
    int t1 = t0 + 8;
    #pragma unroll
    for (int ni = 0; ni < 4; ni++){
        int d = wn + ni*8 + (lane & 3)*2;
        #pragma unroll
        for (int half = 0; half < 2; half++){
            int t = half ? t1 : t0;
            if (t >= LT_) continue;
            __half2 hh = __floats2half2_rn(acc[ni][half*2]*DESCALE,
                                           acc[ni][half*2+1]*DESCALE);
            *(uint32_t*)&g_xh[((size_t)t*NB_ + n)*E_ + h*HD_ + d] = *(uint32_t*)&hh;
        }
    }
}

// ---------------- threefry2x32 (bit-exact JAX, partitionable) ----------------
__device__ __forceinline__ uint32_t rotl32(uint32_t x, int r){ return (x<<r)|(x>>(32-r)); }

__device__ __forceinline__ void tf2x32(uint32_t k0, uint32_t k1, uint32_t x0, uint32_t x1,
                                       uint32_t &o0, uint32_t &o1)
{
    uint32_t ks2 = k0 ^ k1 ^ 0x1BD11BDAu;
#define TFR(r) { x0 += x1; x1 = rotl32(x1, (r)); x1 ^= x0; }
    x0 += k0; x1 += k1;
    TFR(13) TFR(15) TFR(26) TFR(6)
    x0 += k1;  x1 += ks2 + 1u;
    TFR(17) TFR(29) TFR(16) TFR(24)
    x0 += ks2; x1 += k0 + 2u;
    TFR(13) TFR(15) TFR(26) TFR(6)
    x0 += k0;  x1 += k1 + 3u;
    TFR(17) TFR(29) TFR(16) TFR(24)
    x0 += k1;  x1 += ks2 + 4u;
    TFR(13) TFR(15) TFR(26) TFR(6)
    x0 += ks2; x1 += k0 + 5u;
#undef TFR
    o0 = x0; o1 = x1;
}

__device__ __forceinline__ uint32_t rbits32(uint32_t ka, uint32_t kb, uint32_t i){
    uint32_t o0, o1;
    tf2x32(ka, kb, 0u, i, o0, o1);
    return o0 ^ o1;
}

__device__ __forceinline__ float u01(uint32_t bits){
    return __uint_as_float((bits >> 9) | 0x3f800000u) - 1.0f;
}

__device__ __forceinline__ float blockSum256(float v, float* red){
    #pragma unroll
    for (int o=16;o>0;o>>=1) v += __shfl_xor_sync(0xffffffffu, v, o);
    __syncthreads();
    if ((threadIdx.x & 31) == 0) red[threadIdx.x >> 5] = v;
    __syncthreads();
    float s = red[0];
    #pragma unroll
    for (int i=1;i<8;i++) s += red[i];
    return s;
}

__device__ __forceinline__ float warpSum(float v){
    #pragma unroll
    for (int o=16;o>0;o>>=1) v += __shfl_xor_sync(0xffffffffu, v, o);
    return v;
}

// ---------------- 3. random rows: warp-per-sample, fused softmax -> fp16 probs ------
__global__ __launch_bounds__(256) void rand_kernel()
{
    int b   = blockIdx.x;
    int tid = threadIdx.x, lid = tid & 31, wid = tid >> 5;
    __shared__ float u[L_];
    __shared__ float red[8];
    __shared__ float norm_sh;

    uint32_t k1a, k1b, k2a, k2b;
    tf2x32(0u, 1234u, 0u, 0u, k1a, k1b);
    tf2x32(0u, 1234u, 0u, 1u, k2a, k2b);

    float c = 0.f;
    if (tid < L_) c = g_attn[(size_t)b*LT_*LP_ + tid];
    float ss = blockSum256(c*c, red);
    if (tid == 0) norm_sh = sqrtf(ss);
    __syncthreads();
    float norm = norm_sh;
    float nden = fmaxf(norm, 1e-12f);
    if (tid < L_) u[tid] = c / nden;
    __syncthreads();

    for (int n = wid; n < NS_; n += 8){
        float fc = u01(rbits32(k2a, k2b, (uint32_t)n));
        float cosn = fc * 0.2f + 0.7f;
        float sinn = sqrtf(1.0f - cosn*cosn);

        float r[7], uu[7];
        float dot = 0.f;
        uint32_t base = ((uint32_t)n*1536u + (uint32_t)b)*197u;
        #pragma unroll
        for (int i = 0; i < 7; i++){
            int idx = i*32 + lid;
            if (idx < L_){
                r[i]  = u01(rbits32(k1a, k1b, base + (uint32_t)idx)) * 2.0f - 1.0f;
                uu[i] = u[idx];
            } else { r[i] = 0.f; uu[i] = 0.f; }
            dot += r[i]*uu[i];
        }
        dot = warpSum(dot);
        float tsum = 0.f;
        #pragma unroll
        for (int i = 0; i < 7; i++){
            r[i] = r[i] - dot*uu[i];
            tsum += r[i]*r[i];
        }
        tsum = warpSum(tsum);
        float inv = 1.0f / fmaxf(sqrtf(tsum), 1e-12f);

        float w[7];
        float m = NEG_INF;
        #pragma unroll
        for (int i = 0; i < 7; i++){
            int idx = i*32 + lid;
            w[i] = (idx < L_) ? (cosn*uu[i] + sinn*(r[i]*inv)) * norm : NEG_INF;
            m = fmaxf(m, w[i]);
        }
        #pragma unroll
        for (int o=16;o>0;o>>=1) m = fmaxf(m, __shfl_xor_sync(0xffffffffu, m, o));
        float s = 0.f;
        #pragma unroll
        for (int i = 0; i < 7; i++){
            w[i] = expf(w[i] - m);
            s += w[i];
        }
        s = warpSum(s);
        float sinv = 1.0f / s;

        __half* dst = &g_p16[((size_t)b*LT_ + 1 + n)*LP_];
        #pragma unroll
        for (int i = 0; i < 7; i++){
            int idx = i*32 + lid;
            if (idx < L_) dst[idx] = __float2half_rn(w[i] * sinv);
            else if (idx < LP_) dst[idx] = __ushort_as_half((unsigned short)0);
        }
    }
}

// ---------------- 7. attn_weights = mean over heads (fp16 probs) ----------------
__global__ __launch_bounds__(256) void mean_kernel(float* __restrict__ aw)
{
    int idx = blockIdx.x * 256 + threadIdx.x;
    if (idx >= AW_ELEMS) return;
    int s = idx % L_;
    int t = (idx / L_) % LT_;
    int n = idx / (L_ * LT_);
    float sum = 0.f;
    #pragma unroll
    for (int h=0; h<H_; h++)
        sum += __half2float(g_p16[(((size_t)(n*H_ + h))*LT_ + t)*LP_ + s]);
    aw[idx] = sum * (1.0f/12.0f);
}

// ---------------- launch ----------------
extern "C" void kernel_launch(void* const* d_in, const int* in_sizes, int n_in,
                              void* d_out, int out_size)
{
    const float* q   = (const float*)d_in[0];
    const float* k   = (const float*)d_in[1];
    const float* v   = (const float*)d_in[2];
    const float* ipw = (const float*)d_in[3];
    const float* ipb = (const float*)d_in[4];
    const float* opw = (const float*)d_in[5];
    const float* opb = (const float*)d_in[6];
    float* out = (float*)d_out;

    __half *ah, *wh, *wl;
    cudaGetSymbolAddress((void**)&ah, g_ah);
    cudaGetSymbolAddress((void**)&wh, g_wh);
    cudaGetSymbolAddress((void**)&wl, g_wl);

    const int n4in = IN_ELEMS/4;
    round_all<<<dim3((n4in+255)/256, 3), 256>>>(q, k, v, ah, n4in);
    splitw_all<<<(4*W_ELEMS/4+255)/256, 256>>>(ipw, opw, wh, wl);

    proj_tc<<<dim3(6,197,3), 256>>>(ipb);
    qk_mma<<<dim3(1536,4), 256>>>();
    rand_kernel<<<1536, 256>>>();
    av_mma<<<dim3(1536,5), 256>>>();
    out_tc<<<dim3(6,257), 256>>>(opb, out);
    mean_kernel<<<(AW_ELEMS + 255)/256, 256>>>(out + OUT_ELEMS);
}